// round 13
// baseline (speedup 1.0000x reference)
#include <cuda_runtime.h>
#include <math.h>
#include <stdint.h>

#define N_NODES 20000
#define N_EDGES 320000
#define FIN 128
#define HC 320
#define NHEAD 10
#define CH 32
#define B_GRAPHS 64
#define NEG_SLOPE 0.2f
#define BN_EPS 1e-5f

// ---------------- scratch (device globals; no allocs allowed) ----------------
__device__ float  g_xl[(size_t)N_NODES * HC];        // 25.6 MB
__device__ float  g_xr[(size_t)N_NODES * HC];        // 25.6 MB
__device__ float4 g_sumattr4[(size_t)N_NODES * FIN / 4];  // 10.24 MB
__device__ int    g_cnt[N_NODES];
__device__ float  g_p[(size_t)N_EDGES * NHEAD];      // 12.8 MB  exp(score) per edge
__device__ float  g_pself[(size_t)N_NODES * NHEAD];
__device__ float  g_denom[(size_t)N_NODES * NHEAD];
__device__ float  g_acc[(size_t)N_NODES * CH];
__device__ float  g_gsum[B_GRAPHS * CH];
__device__ int    g_gcnt[B_GRAPHS];

// ---------------- zero scratch ----------------
__global__ void zero_bufs() {
    int i0 = blockIdx.x * blockDim.x + threadIdx.x;
    int stride = gridDim.x * blockDim.x;
    float4 z4 = make_float4(0.f, 0.f, 0.f, 0.f);
    for (int i = i0; i < N_NODES * FIN / 4; i += stride) g_sumattr4[i] = z4;
    for (int i = i0; i < N_NODES; i += stride) g_cnt[i] = 0;
    for (int i = i0; i < N_NODES * NHEAD; i += stride) g_denom[i] = 0.f;
    for (int i = i0; i < N_NODES * CH; i += stride) g_acc[i] = 0.f;
    for (int i = i0; i < B_GRAPHS * CH; i += stride) g_gsum[i] = 0.f;
    for (int i = i0; i < B_GRAPHS; i += stride) g_gcnt[i] = 0;
}

// ---------------- segment-sum of edge_attr by dst (vector red) ----------------
__device__ __forceinline__ void red_add_f4(float4* addr, float4 v) {
    asm volatile("red.global.add.v4.f32 [%0], {%1,%2,%3,%4};"
                 :: "l"(addr), "f"(v.x), "f"(v.y), "f"(v.z), "f"(v.w) : "memory");
}

__global__ void scatter_attr(const float* __restrict__ ea, const int* __restrict__ ei) {
    int t = blockIdx.x * blockDim.x + threadIdx.x;
    int edge = t >> 5;
    int lane = t & 31;
    if (edge >= N_EDGES) return;
    int dst = ei[N_EDGES + edge];
    float4 v = ((const float4*)(ea + (size_t)edge * FIN))[lane];
    red_add_f4(&g_sumattr4[(size_t)dst * (FIN / 4) + lane], v);
    if (lane == 0) atomicAdd(&g_cnt[dst], 1);
}

// ---------------- x_l / x_r FFMA GEMM (exact fp32: these are the message values) ---
// A = BN(x) [N x 128], B = [W_l | W_r] (640 virtual cols), store x_l / x_r
__global__ __launch_bounds__(256)
void xlr_kernel(const float* __restrict__ Asrc,
                const float* __restrict__ Wl, const float* __restrict__ Wr,
                const float* __restrict__ bl, const float* __restrict__ br,
                const float* __restrict__ bn_g, const float* __restrict__ bn_b,
                const float* __restrict__ bn_m, const float* __restrict__ bn_v) {
    __shared__ float smem[10304];
    __shared__ float s_bnsc[FIN], s_bnsh[FIN];
    float* As = smem;            // 2048 floats, swizzled transposed
    float* Bs = smem + 2048;     // 5120 floats

    const int tid = threadIdx.x;
    const int row0 = blockIdx.x * 64;
    const int n0 = blockIdx.y * 160;

    const float* Bptr;
    const float* biasp;
    int ncol0;
    if (n0 < HC) { Bptr = Wl; biasp = bl; ncol0 = n0; }
    else         { Bptr = Wr; biasp = br; ncol0 = n0 - HC; }

    if (tid < FIN) {
        float sc = bn_g[tid] * rsqrtf(bn_v[tid] + BN_EPS);
        s_bnsc[tid] = sc;
        s_bnsh[tid] = bn_b[tid] - bn_m[tid] * sc;
    }
    __syncthreads();

    float acc[4][10];
#pragma unroll
    for (int r = 0; r < 4; r++)
#pragma unroll
        for (int j = 0; j < 10; j++) acc[r][j] = 0.f;

    const int ty = tid >> 4;
    const int tx = tid & 15;

    for (int kc = 0; kc < FIN; kc += 32) {
#pragma unroll
        for (int j = 0; j < 2; j++) {
            int i = tid + j * 256;
            int r = i >> 3;
            int c4 = i & 7;
            int grow = row0 + r;
            float4 v = make_float4(0.f, 0.f, 0.f, 0.f);
            if (grow < N_NODES) {
                v = *(const float4*)(Asrc + (size_t)grow * FIN + kc + c4 * 4);
                int kb = kc + c4 * 4;
                v.x = v.x * s_bnsc[kb + 0] + s_bnsh[kb + 0];
                v.y = v.y * s_bnsc[kb + 1] + s_bnsh[kb + 1];
                v.z = v.z * s_bnsc[kb + 2] + s_bnsh[kb + 2];
                v.w = v.w * s_bnsc[kb + 3] + s_bnsh[kb + 3];
            }
            int m2 = r ^ (c4 << 2);
            As[(c4 * 4 + 0) * 64 + m2] = v.x;
            As[(c4 * 4 + 1) * 64 + m2] = v.y;
            As[(c4 * 4 + 2) * 64 + m2] = v.z;
            As[(c4 * 4 + 3) * 64 + m2] = v.w;
        }
#pragma unroll
        for (int j = 0; j < 5; j++) {
            int i = tid + j * 256;
            int kk = i / 40;
            int n4 = i % 40;
            float4 v = *(const float4*)(Bptr + (size_t)(kc + kk) * HC + ncol0 + n4 * 4);
            *(float4*)(Bs + kk * 160 + n4 * 4) = v;
        }
        __syncthreads();

#pragma unroll 8
        for (int k = 0; k < 32; k++) {
            float4 a = *(const float4*)(As + k * 64 + ((ty * 4) ^ (((k >> 2) & 7) << 2)));
            const float* bb = Bs + k * 160 + tx * 10;
            float bv[10];
            float2 t0 = *(const float2*)(bb + 0);
            float2 t1 = *(const float2*)(bb + 2);
            float2 t2 = *(const float2*)(bb + 4);
            float2 t3 = *(const float2*)(bb + 6);
            float2 t4 = *(const float2*)(bb + 8);
            bv[0] = t0.x; bv[1] = t0.y; bv[2] = t1.x; bv[3] = t1.y; bv[4] = t2.x;
            bv[5] = t2.y; bv[6] = t3.x; bv[7] = t3.y; bv[8] = t4.x; bv[9] = t4.y;
#pragma unroll
            for (int j = 0; j < 10; j++) {
                acc[0][j] += a.x * bv[j];
                acc[1][j] += a.y * bv[j];
                acc[2][j] += a.z * bv[j];
                acc[3][j] += a.w * bv[j];
            }
        }
        __syncthreads();
    }

    float* outp = (n0 < HC) ? g_xl : g_xr;
#pragma unroll
    for (int r = 0; r < 4; r++) {
        int grow = row0 + ty * 4 + r;
        if (grow < N_NODES) {
#pragma unroll
            for (int j = 0; j < 10; j++) {
                int cl = tx * 10 + j;
                outp[(size_t)grow * HC + ncol0 + cl] = acc[r][j] + biasp[ncol0 + cl];
            }
        }
    }
}

// ---------------- tf32 tensor-core score GEMM + fused attention epilogue ----------
// MODE 1: A = edge_attr [E x 128] @ W_e ; MODE 2: A = sumattr/cnt [N x 128] @ W_e
// Tile M=64, N=160, K=32 x 4 iters; 8 warps as 2(M) x 4(N); warp tile 32x40.
// Grid: (nhalves, rowblocks) — nhalf FAST so both halves of the same A rows run
// adjacently: edge_attr streamed from DRAM once, second half hits L2.

// NOTE: cvt.rna.tf32.f32 requires a .b32 destination register -> "=r" constraint.
__device__ __forceinline__ uint32_t to_tf32(float x) {
    uint32_t r;
    asm("cvt.rna.tf32.f32 %0, %1;" : "=r"(r) : "f"(x));
    return r;
}

#define MMA_TF32(c, a, b)                                                      \
    asm volatile(                                                              \
        "mma.sync.aligned.m16n8k8.row.col.f32.tf32.tf32.f32 "                  \
        "{%0,%1,%2,%3}, {%4,%5,%6,%7}, {%8,%9}, {%0,%1,%2,%3};"                \
        : "+f"(c[0]), "+f"(c[1]), "+f"(c[2]), "+f"(c[3])                       \
        : "r"(a[0]), "r"(a[1]), "r"(a[2]), "r"(a[3]), "r"(b[0]), "r"(b[1]))

template <int MODE>
__global__ __launch_bounds__(256, 2)
void score_gemm(const float* __restrict__ Asrc, const float* __restrict__ We,
                const float* __restrict__ att, const int* __restrict__ ei) {
    __shared__ float sm[10560];           // As[64][36] + Bs[32][164]; reused as zsm[64][165]
    __shared__ int s_src[64], s_dst[64];
    __shared__ float s_rinv[64];
    float* As = sm;                        // stride 36 (tf32 bit patterns)
    float* Bs = sm + 2304;                 // stride 164
    uint32_t* Asu = (uint32_t*)As;
    uint32_t* Bsu = (uint32_t*)Bs;

    const int tid = threadIdx.x;
    const int n0 = blockIdx.x * 160;       // n-half FAST dim -> A rows L2-reused
    const int row0 = blockIdx.y * 64;
    const int warp = tid >> 5, lane = tid & 31;
    const int g = lane >> 2, tg = lane & 3;
    const int wm = warp >> 2, wn = warp & 3;

    if (MODE == 1) {
        if (tid < 64) {
            s_src[tid] = ei[row0 + tid];
            s_dst[tid] = ei[N_EDGES + row0 + tid];
        }
    } else {
        if (tid < 64) {
            int node = row0 + tid;
            int ok = (node < N_NODES);
            int c = ok ? g_cnt[node] : 1;
            if (c < 1) c = 1;
            s_rinv[tid] = 1.0f / (float)c;
            s_src[tid] = ok ? node : 0;
            s_dst[tid] = s_src[tid];
        }
    }

    float acc[2][5][4];
#pragma unroll
    for (int mi = 0; mi < 2; mi++)
#pragma unroll
        for (int nt = 0; nt < 5; nt++)
#pragma unroll
            for (int q = 0; q < 4; q++) acc[mi][nt][q] = 0.f;

    for (int kc = 0; kc < FIN; kc += 32) {
        __syncthreads();
        // --- stage A tile: [64 rows][32 k], row stride 36 (16B-aligned, conflict-free frags)
#pragma unroll
        for (int j = 0; j < 2; j++) {
            int i = tid + j * 256;             // 0..511 float4 slots
            int r = i >> 3;
            int c4 = i & 7;
            float4 v;
            if (MODE == 1) {
                v = *(const float4*)(Asrc + (size_t)(row0 + r) * FIN + kc + c4 * 4);
            } else {
                int grow = row0 + r;
                if (grow < N_NODES) {
                    v = *(const float4*)((const float*)g_sumattr4 + (size_t)grow * FIN + kc + c4 * 4);
                    float s = s_rinv[r];
                    v.x *= s; v.y *= s; v.z *= s; v.w *= s;
                } else {
                    v = make_float4(0.f, 0.f, 0.f, 0.f);
                }
            }
            uint4 u;
            u.x = to_tf32(v.x); u.y = to_tf32(v.y); u.z = to_tf32(v.z); u.w = to_tf32(v.w);
            *(uint4*)(Asu + r * 36 + c4 * 4) = u;
        }
        // --- stage B tile: [32 k][160 n], row stride 164
#pragma unroll
        for (int j = 0; j < 5; j++) {
            int i = tid + j * 256;             // 0..1279 float4 slots
            int kk = i / 40;
            int n4 = i % 40;
            float4 v = *(const float4*)(We + (size_t)(kc + kk) * HC + n0 + n4 * 4);
            uint4 u;
            u.x = to_tf32(v.x); u.y = to_tf32(v.y); u.z = to_tf32(v.z); u.w = to_tf32(v.w);
            *(uint4*)(Bsu + kk * 164 + n4 * 4) = u;
        }
        __syncthreads();

#pragma unroll
        for (int k8 = 0; k8 < 32; k8 += 8) {
            uint32_t a[2][4], b[5][2];
#pragma unroll
            for (int mi = 0; mi < 2; mi++) {
                int m = wm * 32 + mi * 16;
                a[mi][0] = Asu[(m + g) * 36 + k8 + tg];
                a[mi][1] = Asu[(m + g + 8) * 36 + k8 + tg];
                a[mi][2] = Asu[(m + g) * 36 + k8 + tg + 4];
                a[mi][3] = Asu[(m + g + 8) * 36 + k8 + tg + 4];
            }
#pragma unroll
            for (int nt = 0; nt < 5; nt++) {
                int n = wn * 40 + nt * 8 + g;
                b[nt][0] = Bsu[(k8 + tg) * 164 + n];
                b[nt][1] = Bsu[(k8 + tg + 4) * 164 + n];
            }
#pragma unroll
            for (int mi = 0; mi < 2; mi++)
#pragma unroll
                for (int nt = 0; nt < 5; nt++)
                    MMA_TF32(acc[mi][nt], a[mi], b[nt]);
        }
    }
    __syncthreads();

    // --- epilogue: z = leaky(e + xl[src] + xr[dst]); stage z*att into zsm (stride 165)
    float* zsm = sm;
#pragma unroll
    for (int mi = 0; mi < 2; mi++) {
        int r0 = wm * 32 + mi * 16 + g;        // rows r0 and r0+8
        int s0 = s_src[r0], d0 = s_dst[r0];
        int s1 = s_src[r0 + 8], d1 = s_dst[r0 + 8];
        const float* xl0 = g_xl + (size_t)s0 * HC + n0;
        const float* xr0 = g_xr + (size_t)d0 * HC + n0;
        const float* xl1 = g_xl + (size_t)s1 * HC + n0;
        const float* xr1 = g_xr + (size_t)d1 * HC + n0;
#pragma unroll
        for (int nt = 0; nt < 5; nt++) {
            int cB = wn * 40 + nt * 8 + 2 * tg;
            float at0 = att[n0 + cB], at1 = att[n0 + cB + 1];
            float z;
            z = acc[mi][nt][0] + xl0[cB] + xr0[cB];
            z = (z > 0.f) ? z : NEG_SLOPE * z;
            zsm[r0 * 165 + cB] = z * at0;
            z = acc[mi][nt][1] + xl0[cB + 1] + xr0[cB + 1];
            z = (z > 0.f) ? z : NEG_SLOPE * z;
            zsm[r0 * 165 + cB + 1] = z * at1;
            z = acc[mi][nt][2] + xl1[cB] + xr1[cB];
            z = (z > 0.f) ? z : NEG_SLOPE * z;
            zsm[(r0 + 8) * 165 + cB] = z * at0;
            z = acc[mi][nt][3] + xl1[cB + 1] + xr1[cB + 1];
            z = (z > 0.f) ? z : NEG_SLOPE * z;
            zsm[(r0 + 8) * 165 + cB + 1] = z * at1;
        }
    }
    __syncthreads();

    // --- per (row, head) sum over 32 channels -> p = exp(score); denom atomics
    for (int task = tid; task < 320; task += 256) {
        int row = task & 63;
        int hh = task >> 6;                    // 0..4 (this n-half covers 5 heads)
        float s = 0.f;
#pragma unroll
        for (int i = 0; i < 32; i++) s += zsm[row * 165 + hh * 32 + i];
        float p = expf(s);
        int hg = blockIdx.x * 5 + hh;
        if (MODE == 1) {
            int e = row0 + row;
            g_p[(size_t)e * NHEAD + hg] = p;
            atomicAdd(&g_denom[(size_t)s_dst[row] * NHEAD + hg], p);
        } else {
            int node = row0 + row;
            if (node < N_NODES) {
                g_pself[(size_t)node * NHEAD + hg] = p;
                atomicAdd(&g_denom[(size_t)node * NHEAD + hg], p);
            }
        }
    }
}

// ---------------- edge message pass: acc[dst] += sum_h alpha_h * xl[src,h,:] ----------------
__global__ void edge_msg(const int* __restrict__ ei) {
    int gwarp = (blockIdx.x * blockDim.x + threadIdx.x) >> 5;
    int lane = threadIdx.x & 31;
    if (gwarp >= N_EDGES) return;
    int src = ei[gwarp];
    int dst = ei[N_EDGES + gwarp];
    float alpha = 0.f;
    if (lane < NHEAD)
        alpha = g_p[(size_t)gwarp * NHEAD + lane] / g_denom[(size_t)dst * NHEAD + lane];
    const float* xl = g_xl + (size_t)src * HC;
    float m = 0.f;
#pragma unroll
    for (int h = 0; h < NHEAD; h++) {
        float a = __shfl_sync(0xffffffff, alpha, h);
        m += a * xl[h * CH + lane];
    }
    atomicAdd(&g_acc[(size_t)dst * CH + lane], m);
}

// ---------------- node finalize + global mean pool (smem-staged atomics) ----------------
__global__ void finalize_pool(const int* __restrict__ batch, const float* __restrict__ bias_gat) {
    __shared__ float s_gsum[B_GRAPHS * CH];
    __shared__ int s_gcnt[B_GRAPHS];
    int tid = threadIdx.x;
    for (int i = tid; i < B_GRAPHS * CH; i += 256) s_gsum[i] = 0.f;
    if (tid < B_GRAPHS) s_gcnt[tid] = 0;
    __syncthreads();

    int warp = tid >> 5, lane = tid & 31;
    for (int u = 0; u < 8; u++) {
        int node = blockIdx.x * 64 + warp * 8 + u;
        if (node < N_NODES) {
            int b = batch[node];
            float a = 0.f;
            if (lane < NHEAD)
                a = g_pself[(size_t)node * NHEAD + lane] / g_denom[(size_t)node * NHEAD + lane];
            const float* xl = g_xl + (size_t)node * HC;
            float selfm = 0.f;
#pragma unroll
            for (int h = 0; h < NHEAD; h++) {
                float ah = __shfl_sync(0xffffffff, a, h);
                selfm += ah * xl[h * CH + lane];
            }
            float v = (g_acc[(size_t)node * CH + lane] + selfm) * (1.0f / NHEAD) + bias_gat[lane];
            v = fmaxf(v, 0.f);
            atomicAdd(&s_gsum[b * CH + lane], v);
            if (lane == 0) atomicAdd(&s_gcnt[b], 1);
        }
    }
    __syncthreads();
    for (int i = tid; i < B_GRAPHS * CH; i += 256)
        if (s_gsum[i] != 0.f) atomicAdd(&g_gsum[i], s_gsum[i]);
    if (tid < B_GRAPHS && s_gcnt[tid] != 0) atomicAdd(&g_gcnt[tid], s_gcnt[tid]);
}

// ---------------- head: out[b, o] = (gsum[b]/cnt[b]) @ W_head + b_head ----------------
__global__ void head_kernel(const float* __restrict__ Wh, const float* __restrict__ bh,
                            float* __restrict__ out) {
    int t = threadIdx.x;
    if (t < B_GRAPHS * 2) {
        int b = t >> 1, o = t & 1;
        int c = g_gcnt[b]; if (c < 1) c = 1;
        float inv = 1.0f / (float)c;
        float s = 0.f;
#pragma unroll
        for (int k = 0; k < CH; k++) s += (g_gsum[b * CH + k] * inv) * Wh[k * 2 + o];
        out[t] = s + bh[o];
    }
}

extern "C" void kernel_launch(void* const* d_in, const int* in_sizes, int n_in,
                              void* d_out, int out_size) {
    const float* x        = (const float*)d_in[0];
    const int*   ei       = (const int*)d_in[1];
    const float* ea       = (const float*)d_in[2];
    const int*   batch    = (const int*)d_in[3];
    const float* bn_g     = (const float*)d_in[4];
    const float* bn_b     = (const float*)d_in[5];
    const float* bn_m     = (const float*)d_in[6];
    const float* bn_v     = (const float*)d_in[7];
    const float* Wl       = (const float*)d_in[8];
    const float* bl       = (const float*)d_in[9];
    const float* Wr       = (const float*)d_in[10];
    const float* br       = (const float*)d_in[11];
    const float* We       = (const float*)d_in[12];
    const float* att      = (const float*)d_in[13];
    const float* bias_gat = (const float*)d_in[14];
    const float* Wh       = (const float*)d_in[15];
    const float* bh       = (const float*)d_in[16];
    float* out = (float*)d_out;

    zero_bufs<<<512, 256>>>();
    scatter_attr<<<(N_EDGES * 32) / 256, 256>>>(ea, ei);
    // x_l / x_r : exact fp32 (message values)
    xlr_kernel<<<dim3(313, 4), 256>>>(x, Wl, Wr, bl, br, bn_g, bn_b, bn_m, bn_v);
    // self-loop scores (tf32 tensor cores)
    score_gemm<2><<<dim3(2, 313), 256>>>(nullptr, We, att, ei);
    // edge scores: 26-GFLOP GEMM, tf32 tensor cores, nhalf-fast grid for L2 reuse
    score_gemm<1><<<dim3(2, 5000), 256>>>(ea, We, att, ei);
    edge_msg<<<(N_EDGES * 32) / 256, 256>>>(ei);
    finalize_pool<<<313, 256>>>(batch, bias_gat);
    head_kernel<<<1, 128>>>(Wh, bh, out);
}

// round 14
// speedup vs baseline: 1.0683x; 1.0683x over previous
#include <cuda_runtime.h>
#include <math.h>
#include <stdint.h>

#define N_NODES 20000
#define N_EDGES 320000
#define FIN 128
#define HC 320
#define NHEAD 10
#define CH 32
#define B_GRAPHS 64
#define NEG_SLOPE 0.2f
#define BN_EPS 1e-5f

// ---------------- scratch (device globals; no allocs allowed) ----------------
__device__ float  g_xl[(size_t)N_NODES * HC];        // 25.6 MB
__device__ float  g_xr[(size_t)N_NODES * HC];        // 25.6 MB
__device__ float4 g_sumattr4[(size_t)N_NODES * FIN / 4];  // 10.24 MB
__device__ int    g_cnt[N_NODES];
__device__ float  g_p[(size_t)N_EDGES * NHEAD];      // 12.8 MB  exp(score) per edge
__device__ float  g_pself[(size_t)N_NODES * NHEAD];
__device__ float  g_denom[(size_t)N_NODES * NHEAD];
__device__ float  g_acc[(size_t)N_NODES * CH];
__device__ float  g_gsum[B_GRAPHS * CH];
__device__ int    g_gcnt[B_GRAPHS];

// ---------------- zero scratch ----------------
__global__ void zero_bufs() {
    int i0 = blockIdx.x * blockDim.x + threadIdx.x;
    int stride = gridDim.x * blockDim.x;
    float4 z4 = make_float4(0.f, 0.f, 0.f, 0.f);
    for (int i = i0; i < N_NODES * FIN / 4; i += stride) g_sumattr4[i] = z4;
    for (int i = i0; i < N_NODES; i += stride) g_cnt[i] = 0;
    for (int i = i0; i < N_NODES * NHEAD; i += stride) g_denom[i] = 0.f;
    for (int i = i0; i < N_NODES * CH; i += stride) g_acc[i] = 0.f;
    for (int i = i0; i < B_GRAPHS * CH; i += stride) g_gsum[i] = 0.f;
    for (int i = i0; i < B_GRAPHS; i += stride) g_gcnt[i] = 0;
}

// ---------------- segment-sum of edge_attr by dst (vector red) ----------------
__device__ __forceinline__ void red_add_f4(float4* addr, float4 v) {
    asm volatile("red.global.add.v4.f32 [%0], {%1,%2,%3,%4};"
                 :: "l"(addr), "f"(v.x), "f"(v.y), "f"(v.z), "f"(v.w) : "memory");
}

__global__ void scatter_attr(const float* __restrict__ ea, const int* __restrict__ ei) {
    int t = blockIdx.x * blockDim.x + threadIdx.x;
    int edge = t >> 5;
    int lane = t & 31;
    if (edge >= N_EDGES) return;
    int dst = ei[N_EDGES + edge];
    float4 v = ((const float4*)(ea + (size_t)edge * FIN))[lane];
    red_add_f4(&g_sumattr4[(size_t)dst * (FIN / 4) + lane], v);
    if (lane == 0) atomicAdd(&g_cnt[dst], 1);
}

// ---------------- x_l / x_r FFMA GEMM (exact fp32: these are the message values) ---
// A = BN(x) [N x 128], B = [W_l | W_r] (640 virtual cols), store x_l / x_r
__global__ __launch_bounds__(256)
void xlr_kernel(const float* __restrict__ Asrc,
                const float* __restrict__ Wl, const float* __restrict__ Wr,
                const float* __restrict__ bl, const float* __restrict__ br,
                const float* __restrict__ bn_g, const float* __restrict__ bn_b,
                const float* __restrict__ bn_m, const float* __restrict__ bn_v) {
    __shared__ float smem[10304];
    __shared__ float s_bnsc[FIN], s_bnsh[FIN];
    float* As = smem;            // 2048 floats, swizzled transposed
    float* Bs = smem + 2048;     // 5120 floats

    const int tid = threadIdx.x;
    const int row0 = blockIdx.x * 64;
    const int n0 = blockIdx.y * 160;

    const float* Bptr;
    const float* biasp;
    int ncol0;
    if (n0 < HC) { Bptr = Wl; biasp = bl; ncol0 = n0; }
    else         { Bptr = Wr; biasp = br; ncol0 = n0 - HC; }

    if (tid < FIN) {
        float sc = bn_g[tid] * rsqrtf(bn_v[tid] + BN_EPS);
        s_bnsc[tid] = sc;
        s_bnsh[tid] = bn_b[tid] - bn_m[tid] * sc;
    }
    __syncthreads();

    float acc[4][10];
#pragma unroll
    for (int r = 0; r < 4; r++)
#pragma unroll
        for (int j = 0; j < 10; j++) acc[r][j] = 0.f;

    const int ty = tid >> 4;
    const int tx = tid & 15;

    for (int kc = 0; kc < FIN; kc += 32) {
#pragma unroll
        for (int j = 0; j < 2; j++) {
            int i = tid + j * 256;
            int r = i >> 3;
            int c4 = i & 7;
            int grow = row0 + r;
            float4 v = make_float4(0.f, 0.f, 0.f, 0.f);
            if (grow < N_NODES) {
                v = *(const float4*)(Asrc + (size_t)grow * FIN + kc + c4 * 4);
                int kb = kc + c4 * 4;
                v.x = v.x * s_bnsc[kb + 0] + s_bnsh[kb + 0];
                v.y = v.y * s_bnsc[kb + 1] + s_bnsh[kb + 1];
                v.z = v.z * s_bnsc[kb + 2] + s_bnsh[kb + 2];
                v.w = v.w * s_bnsc[kb + 3] + s_bnsh[kb + 3];
            }
            int m2 = r ^ (c4 << 2);
            As[(c4 * 4 + 0) * 64 + m2] = v.x;
            As[(c4 * 4 + 1) * 64 + m2] = v.y;
            As[(c4 * 4 + 2) * 64 + m2] = v.z;
            As[(c4 * 4 + 3) * 64 + m2] = v.w;
        }
#pragma unroll
        for (int j = 0; j < 5; j++) {
            int i = tid + j * 256;
            int kk = i / 40;
            int n4 = i % 40;
            float4 v = *(const float4*)(Bptr + (size_t)(kc + kk) * HC + ncol0 + n4 * 4);
            *(float4*)(Bs + kk * 160 + n4 * 4) = v;
        }
        __syncthreads();

#pragma unroll 8
        for (int k = 0; k < 32; k++) {
            float4 a = *(const float4*)(As + k * 64 + ((ty * 4) ^ (((k >> 2) & 7) << 2)));
            const float* bb = Bs + k * 160 + tx * 10;
            float bv[10];
            float2 t0 = *(const float2*)(bb + 0);
            float2 t1 = *(const float2*)(bb + 2);
            float2 t2 = *(const float2*)(bb + 4);
            float2 t3 = *(const float2*)(bb + 6);
            float2 t4 = *(const float2*)(bb + 8);
            bv[0] = t0.x; bv[1] = t0.y; bv[2] = t1.x; bv[3] = t1.y; bv[4] = t2.x;
            bv[5] = t2.y; bv[6] = t3.x; bv[7] = t3.y; bv[8] = t4.x; bv[9] = t4.y;
#pragma unroll
            for (int j = 0; j < 10; j++) {
                acc[0][j] += a.x * bv[j];
                acc[1][j] += a.y * bv[j];
                acc[2][j] += a.z * bv[j];
                acc[3][j] += a.w * bv[j];
            }
        }
        __syncthreads();
    }

    float* outp = (n0 < HC) ? g_xl : g_xr;
#pragma unroll
    for (int r = 0; r < 4; r++) {
        int grow = row0 + ty * 4 + r;
        if (grow < N_NODES) {
#pragma unroll
            for (int j = 0; j < 10; j++) {
                int cl = tx * 10 + j;
                outp[(size_t)grow * HC + ncol0 + cl] = acc[r][j] + biasp[ncol0 + cl];
            }
        }
    }
}

// ---------------- tf32 tensor-core score GEMM + fused attention epilogue ----------
// MODE 1: A = edge_attr [E x 128] @ W_e ; MODE 2: A = sumattr/cnt [N x 128] @ W_e
// Tile M=64, N=160, K=32 x 4 iters; 8 warps as 2(M) x 4(N); warp tile 32x40.
// B smem stride = 168: fragment-load banks (8*tg + 8*nt + g) mod 32 are fully
// disjoint across tg-groups -> conflict-free (stride 164 was 2-way conflicted).

// NOTE: cvt.rna.tf32.f32 requires a .b32 destination register -> "=r" constraint.
__device__ __forceinline__ uint32_t to_tf32(float x) {
    uint32_t r;
    asm("cvt.rna.tf32.f32 %0, %1;" : "=r"(r) : "f"(x));
    return r;
}

#define MMA_TF32(c, a, b)                                                      \
    asm volatile(                                                              \
        "mma.sync.aligned.m16n8k8.row.col.f32.tf32.tf32.f32 "                  \
        "{%0,%1,%2,%3}, {%4,%5,%6,%7}, {%8,%9}, {%0,%1,%2,%3};"                \
        : "+f"(c[0]), "+f"(c[1]), "+f"(c[2]), "+f"(c[3])                       \
        : "r"(a[0]), "r"(a[1]), "r"(a[2]), "r"(a[3]), "r"(b[0]), "r"(b[1]))

#define BSTRIDE 168

template <int MODE>
__global__ __launch_bounds__(256, 2)
void score_gemm(const float* __restrict__ Asrc, const float* __restrict__ We,
                const float* __restrict__ att, const int* __restrict__ ei) {
    __shared__ float sm[10560];           // As[64][36] + Bs[32][168]; reused as zsm[64][165]
    __shared__ int s_src[64], s_dst[64];
    __shared__ float s_rinv[64];
    float* As = sm;                        // stride 36 (tf32 bit patterns)
    float* Bs = sm + 2304;                 // stride 168 (2304+5376=7680 <= 10560)
    uint32_t* Asu = (uint32_t*)As;
    uint32_t* Bsu = (uint32_t*)Bs;

    const int tid = threadIdx.x;
    const int row0 = blockIdx.x * 64;
    const int n0 = blockIdx.y * 160;
    const int warp = tid >> 5, lane = tid & 31;
    const int g = lane >> 2, tg = lane & 3;
    const int wm = warp >> 2, wn = warp & 3;

    if (MODE == 1) {
        if (tid < 64) {
            s_src[tid] = ei[row0 + tid];
            s_dst[tid] = ei[N_EDGES + row0 + tid];
        }
    } else {
        if (tid < 64) {
            int node = row0 + tid;
            int ok = (node < N_NODES);
            int c = ok ? g_cnt[node] : 1;
            if (c < 1) c = 1;
            s_rinv[tid] = 1.0f / (float)c;
            s_src[tid] = ok ? node : 0;
            s_dst[tid] = s_src[tid];
        }
    }

    float acc[2][5][4];
#pragma unroll
    for (int mi = 0; mi < 2; mi++)
#pragma unroll
        for (int nt = 0; nt < 5; nt++)
#pragma unroll
            for (int q = 0; q < 4; q++) acc[mi][nt][q] = 0.f;

    for (int kc = 0; kc < FIN; kc += 32) {
        __syncthreads();
        // --- stage A tile: [64 rows][32 k], row stride 36 (16B-aligned, conflict-free frags)
#pragma unroll
        for (int j = 0; j < 2; j++) {
            int i = tid + j * 256;             // 0..511 float4 slots
            int r = i >> 3;
            int c4 = i & 7;
            float4 v;
            if (MODE == 1) {
                v = *(const float4*)(Asrc + (size_t)(row0 + r) * FIN + kc + c4 * 4);
            } else {
                int grow = row0 + r;
                if (grow < N_NODES) {
                    v = *(const float4*)((const float*)g_sumattr4 + (size_t)grow * FIN + kc + c4 * 4);
                    float s = s_rinv[r];
                    v.x *= s; v.y *= s; v.z *= s; v.w *= s;
                } else {
                    v = make_float4(0.f, 0.f, 0.f, 0.f);
                }
            }
            uint4 u;
            u.x = to_tf32(v.x); u.y = to_tf32(v.y); u.z = to_tf32(v.z); u.w = to_tf32(v.w);
            *(uint4*)(Asu + r * 36 + c4 * 4) = u;
        }
        // --- stage B tile: [32 k][160 n], row stride 168
#pragma unroll
        for (int j = 0; j < 5; j++) {
            int i = tid + j * 256;             // 0..1279 float4 slots
            int kk = i / 40;
            int n4 = i % 40;
            float4 v = *(const float4*)(We + (size_t)(kc + kk) * HC + n0 + n4 * 4);
            uint4 u;
            u.x = to_tf32(v.x); u.y = to_tf32(v.y); u.z = to_tf32(v.z); u.w = to_tf32(v.w);
            *(uint4*)(Bsu + kk * BSTRIDE + n4 * 4) = u;
        }
        __syncthreads();

#pragma unroll
        for (int k8 = 0; k8 < 32; k8 += 8) {
            uint32_t a[2][4], b[5][2];
#pragma unroll
            for (int mi = 0; mi < 2; mi++) {
                int m = wm * 32 + mi * 16;
                a[mi][0] = Asu[(m + g) * 36 + k8 + tg];
                a[mi][1] = Asu[(m + g + 8) * 36 + k8 + tg];
                a[mi][2] = Asu[(m + g) * 36 + k8 + tg + 4];
                a[mi][3] = Asu[(m + g + 8) * 36 + k8 + tg + 4];
            }
#pragma unroll
            for (int nt = 0; nt < 5; nt++) {
                int n = wn * 40 + nt * 8 + g;
                b[nt][0] = Bsu[(k8 + tg) * BSTRIDE + n];
                b[nt][1] = Bsu[(k8 + tg + 4) * BSTRIDE + n];
            }
#pragma unroll
            for (int mi = 0; mi < 2; mi++)
#pragma unroll
                for (int nt = 0; nt < 5; nt++)
                    MMA_TF32(acc[mi][nt], a[mi], b[nt]);
        }
    }
    __syncthreads();

    // --- epilogue: z = leaky(e + xl[src] + xr[dst]); stage z*att into zsm (stride 165)
    float* zsm = sm;
#pragma unroll
    for (int mi = 0; mi < 2; mi++) {
        int r0 = wm * 32 + mi * 16 + g;        // rows r0 and r0+8
        int s0 = s_src[r0], d0 = s_dst[r0];
        int s1 = s_src[r0 + 8], d1 = s_dst[r0 + 8];
        const float* xl0 = g_xl + (size_t)s0 * HC + n0;
        const float* xr0 = g_xr + (size_t)d0 * HC + n0;
        const float* xl1 = g_xl + (size_t)s1 * HC + n0;
        const float* xr1 = g_xr + (size_t)d1 * HC + n0;
#pragma unroll
        for (int nt = 0; nt < 5; nt++) {
            int cB = wn * 40 + nt * 8 + 2 * tg;
            float at0 = att[n0 + cB], at1 = att[n0 + cB + 1];
            float z;
            z = acc[mi][nt][0] + xl0[cB] + xr0[cB];
            z = (z > 0.f) ? z : NEG_SLOPE * z;
            zsm[r0 * 165 + cB] = z * at0;
            z = acc[mi][nt][1] + xl0[cB + 1] + xr0[cB + 1];
            z = (z > 0.f) ? z : NEG_SLOPE * z;
            zsm[r0 * 165 + cB + 1] = z * at1;
            z = acc[mi][nt][2] + xl1[cB] + xr1[cB];
            z = (z > 0.f) ? z : NEG_SLOPE * z;
            zsm[(r0 + 8) * 165 + cB] = z * at0;
            z = acc[mi][nt][3] + xl1[cB + 1] + xr1[cB + 1];
            z = (z > 0.f) ? z : NEG_SLOPE * z;
            zsm[(r0 + 8) * 165 + cB + 1] = z * at1;
        }
    }
    __syncthreads();

    // --- per (row, head) sum over 32 channels -> p = exp(score); denom atomics
    for (int task = tid; task < 320; task += 256) {
        int row = task & 63;
        int hh = task >> 6;                    // 0..4 (this n-half covers 5 heads)
        float s = 0.f;
#pragma unroll
        for (int i = 0; i < 32; i++) s += zsm[row * 165 + hh * 32 + i];
        float p = __expf(s);
        int hg = blockIdx.y * 5 + hh;
        if (MODE == 1) {
            int e = row0 + row;
            g_p[(size_t)e * NHEAD + hg] = p;
            atomicAdd(&g_denom[(size_t)s_dst[row] * NHEAD + hg], p);
        } else {
            int node = row0 + row;
            if (node < N_NODES) {
                g_pself[(size_t)node * NHEAD + hg] = p;
                atomicAdd(&g_denom[(size_t)node * NHEAD + hg], p);
            }
        }
    }
}

// ---------------- edge message pass: acc[dst] += sum_h alpha_h * xl[src,h,:] ----------------
__global__ void edge_msg(const int* __restrict__ ei) {
    int gwarp = (blockIdx.x * blockDim.x + threadIdx.x) >> 5;
    int lane = threadIdx.x & 31;
    if (gwarp >= N_EDGES) return;
    int src = ei[gwarp];
    int dst = ei[N_EDGES + gwarp];
    float alpha = 0.f;
    if (lane < NHEAD)
        alpha = g_p[(size_t)gwarp * NHEAD + lane] / g_denom[(size_t)dst * NHEAD + lane];
    const float* xl = g_xl + (size_t)src * HC;
    float m = 0.f;
#pragma unroll
    for (int h = 0; h < NHEAD; h++) {
        float a = __shfl_sync(0xffffffff, alpha, h);
        m += a * xl[h * CH + lane];
    }
    atomicAdd(&g_acc[(size_t)dst * CH + lane], m);
}

// ---------------- node finalize + global mean pool (smem-staged atomics) ----------------
__global__ void finalize_pool(const int* __restrict__ batch, const float* __restrict__ bias_gat) {
    __shared__ float s_gsum[B_GRAPHS * CH];
    __shared__ int s_gcnt[B_GRAPHS];
    int tid = threadIdx.x;
    for (int i = tid; i < B_GRAPHS * CH; i += 256) s_gsum[i] = 0.f;
    if (tid < B_GRAPHS) s_gcnt[tid] = 0;
    __syncthreads();

    int warp = tid >> 5, lane = tid & 31;
    for (int u = 0; u < 8; u++) {
        int node = blockIdx.x * 64 + warp * 8 + u;
        if (node < N_NODES) {
            int b = batch[node];
            float a = 0.f;
            if (lane < NHEAD)
                a = g_pself[(size_t)node * NHEAD + lane] / g_denom[(size_t)node * NHEAD + lane];
            const float* xl = g_xl + (size_t)node * HC;
            float selfm = 0.f;
#pragma unroll
            for (int h = 0; h < NHEAD; h++) {
                float ah = __shfl_sync(0xffffffff, a, h);
                selfm += ah * xl[h * CH + lane];
            }
            float v = (g_acc[(size_t)node * CH + lane] + selfm) * (1.0f / NHEAD) + bias_gat[lane];
            v = fmaxf(v, 0.f);
            atomicAdd(&s_gsum[b * CH + lane], v);
            if (lane == 0) atomicAdd(&s_gcnt[b], 1);
        }
    }
    __syncthreads();
    for (int i = tid; i < B_GRAPHS * CH; i += 256)
        if (s_gsum[i] != 0.f) atomicAdd(&g_gsum[i], s_gsum[i]);
    if (tid < B_GRAPHS && s_gcnt[tid] != 0) atomicAdd(&g_gcnt[tid], s_gcnt[tid]);
}

// ---------------- head: out[b, o] = (gsum[b]/cnt[b]) @ W_head + b_head ----------------
__global__ void head_kernel(const float* __restrict__ Wh, const float* __restrict__ bh,
                            float* __restrict__ out) {
    int t = threadIdx.x;
    if (t < B_GRAPHS * 2) {
        int b = t >> 1, o = t & 1;
        int c = g_gcnt[b]; if (c < 1) c = 1;
        float inv = 1.0f / (float)c;
        float s = 0.f;
#pragma unroll
        for (int k = 0; k < CH; k++) s += (g_gsum[b * CH + k] * inv) * Wh[k * 2 + o];
        out[t] = s + bh[o];
    }
}

extern "C" void kernel_launch(void* const* d_in, const int* in_sizes, int n_in,
                              void* d_out, int out_size) {
    const float* x        = (const float*)d_in[0];
    const int*   ei       = (const int*)d_in[1];
    const float* ea       = (const float*)d_in[2];
    const int*   batch    = (const int*)d_in[3];
    const float* bn_g     = (const float*)d_in[4];
    const float* bn_b     = (const float*)d_in[5];
    const float* bn_m     = (const float*)d_in[6];
    const float* bn_v     = (const float*)d_in[7];
    const float* Wl       = (const float*)d_in[8];
    const float* bl       = (const float*)d_in[9];
    const float* Wr       = (const float*)d_in[10];
    const float* br       = (const float*)d_in[11];
    const float* We       = (const float*)d_in[12];
    const float* att      = (const float*)d_in[13];
    const float* bias_gat = (const float*)d_in[14];
    const float* Wh       = (const float*)d_in[15];
    const float* bh       = (const float*)d_in[16];
    float* out = (float*)d_out;

    zero_bufs<<<512, 256>>>();
    scatter_attr<<<(N_EDGES * 32) / 256, 256>>>(ea, ei);
    // x_l / x_r : exact fp32 (message values)
    xlr_kernel<<<dim3(313, 4), 256>>>(x, Wl, Wr, bl, br, bn_g, bn_b, bn_m, bn_v);
    // self-loop scores (tf32 tensor cores)
    score_gemm<2><<<dim3(313, 2), 256>>>(nullptr, We, att, ei);
    // edge scores (26-GFLOP GEMM, tf32 tensor cores, fused epilogue)
    score_gemm<1><<<dim3(5000, 2), 256>>>(ea, We, att, ei);
    edge_msg<<<(N_EDGES * 32) / 256, 256>>>(ei);
    finalize_pool<<<313, 256>>>(batch, bias_gat);
    head_kernel<<<1, 128>>>(Wh, bh, out);
}

// round 15
// speedup vs baseline: 1.1845x; 1.1088x over previous
#include <cuda_runtime.h>
#include <math.h>
#include <stdint.h>

#define N_NODES 20000
#define N_EDGES 320000
#define FIN 128
#define HC 320
#define NHEAD 10
#define CH 32
#define B_GRAPHS 64
#define NEG_SLOPE 0.2f
#define BN_EPS 1e-5f

// ---------------- scratch (device globals; no allocs allowed) ----------------
__device__ float  g_xl[(size_t)N_NODES * HC];        // 25.6 MB
__device__ float  g_xr[(size_t)N_NODES * HC];        // 25.6 MB
__device__ float4 g_sumattr4[(size_t)N_NODES * FIN / 4];  // 10.24 MB
__device__ int    g_cnt[N_NODES];
__device__ float  g_p[(size_t)N_EDGES * NHEAD];      // 12.8 MB  exp(score) per edge
__device__ float  g_pself[(size_t)N_NODES * NHEAD];
__device__ float  g_denom[(size_t)N_NODES * NHEAD];
__device__ float  g_acc[(size_t)N_NODES * CH];
__device__ float  g_gsum[B_GRAPHS * CH];
__device__ int    g_gcnt[B_GRAPHS];

// ---------------- zero scratch ----------------
__global__ void zero_bufs() {
    int i0 = blockIdx.x * blockDim.x + threadIdx.x;
    int stride = gridDim.x * blockDim.x;
    float4 z4 = make_float4(0.f, 0.f, 0.f, 0.f);
    for (int i = i0; i < N_NODES * FIN / 4; i += stride) g_sumattr4[i] = z4;
    for (int i = i0; i < N_NODES; i += stride) g_cnt[i] = 0;
    for (int i = i0; i < N_NODES * NHEAD; i += stride) g_denom[i] = 0.f;
    for (int i = i0; i < N_NODES * CH; i += stride) g_acc[i] = 0.f;
    for (int i = i0; i < B_GRAPHS * CH; i += stride) g_gsum[i] = 0.f;
    for (int i = i0; i < B_GRAPHS; i += stride) g_gcnt[i] = 0;
}

// ---------------- segment-sum of edge_attr by dst (vector red) ----------------
__device__ __forceinline__ void red_add_f4(float4* addr, float4 v) {
    asm volatile("red.global.add.v4.f32 [%0], {%1,%2,%3,%4};"
                 :: "l"(addr), "f"(v.x), "f"(v.y), "f"(v.z), "f"(v.w) : "memory");
}

__global__ void scatter_attr(const float* __restrict__ ea, const int* __restrict__ ei) {
    int t = blockIdx.x * blockDim.x + threadIdx.x;
    int edge = t >> 5;
    int lane = t & 31;
    if (edge >= N_EDGES) return;
    int dst = ei[N_EDGES + edge];
    float4 v = ((const float4*)(ea + (size_t)edge * FIN))[lane];
    red_add_f4(&g_sumattr4[(size_t)dst * (FIN / 4) + lane], v);
    if (lane == 0) atomicAdd(&g_cnt[dst], 1);
}

// ---------------- x_l / x_r FFMA GEMM (exact fp32: these are the message values) ---
// A = BN(x) [N x 128], B = [W_l | W_r] (640 virtual cols), store x_l / x_r
__global__ __launch_bounds__(256)
void xlr_kernel(const float* __restrict__ Asrc,
                const float* __restrict__ Wl, const float* __restrict__ Wr,
                const float* __restrict__ bl, const float* __restrict__ br,
                const float* __restrict__ bn_g, const float* __restrict__ bn_b,
                const float* __restrict__ bn_m, const float* __restrict__ bn_v) {
    __shared__ float smem[10304];
    __shared__ float s_bnsc[FIN], s_bnsh[FIN];
    float* As = smem;            // 2048 floats, swizzled transposed
    float* Bs = smem + 2048;     // 5120 floats

    const int tid = threadIdx.x;
    const int row0 = blockIdx.x * 64;
    const int n0 = blockIdx.y * 160;

    const float* Bptr;
    const float* biasp;
    int ncol0;
    if (n0 < HC) { Bptr = Wl; biasp = bl; ncol0 = n0; }
    else         { Bptr = Wr; biasp = br; ncol0 = n0 - HC; }

    if (tid < FIN) {
        float sc = bn_g[tid] * rsqrtf(bn_v[tid] + BN_EPS);
        s_bnsc[tid] = sc;
        s_bnsh[tid] = bn_b[tid] - bn_m[tid] * sc;
    }
    __syncthreads();

    float acc[4][10];
#pragma unroll
    for (int r = 0; r < 4; r++)
#pragma unroll
        for (int j = 0; j < 10; j++) acc[r][j] = 0.f;

    const int ty = tid >> 4;
    const int tx = tid & 15;

    for (int kc = 0; kc < FIN; kc += 32) {
#pragma unroll
        for (int j = 0; j < 2; j++) {
            int i = tid + j * 256;
            int r = i >> 3;
            int c4 = i & 7;
            int grow = row0 + r;
            float4 v = make_float4(0.f, 0.f, 0.f, 0.f);
            if (grow < N_NODES) {
                v = *(const float4*)(Asrc + (size_t)grow * FIN + kc + c4 * 4);
                int kb = kc + c4 * 4;
                v.x = v.x * s_bnsc[kb + 0] + s_bnsh[kb + 0];
                v.y = v.y * s_bnsc[kb + 1] + s_bnsh[kb + 1];
                v.z = v.z * s_bnsc[kb + 2] + s_bnsh[kb + 2];
                v.w = v.w * s_bnsc[kb + 3] + s_bnsh[kb + 3];
            }
            int m2 = r ^ (c4 << 2);
            As[(c4 * 4 + 0) * 64 + m2] = v.x;
            As[(c4 * 4 + 1) * 64 + m2] = v.y;
            As[(c4 * 4 + 2) * 64 + m2] = v.z;
            As[(c4 * 4 + 3) * 64 + m2] = v.w;
        }
#pragma unroll
        for (int j = 0; j < 5; j++) {
            int i = tid + j * 256;
            int kk = i / 40;
            int n4 = i % 40;
            float4 v = *(const float4*)(Bptr + (size_t)(kc + kk) * HC + ncol0 + n4 * 4);
            *(float4*)(Bs + kk * 160 + n4 * 4) = v;
        }
        __syncthreads();

#pragma unroll 8
        for (int k = 0; k < 32; k++) {
            float4 a = *(const float4*)(As + k * 64 + ((ty * 4) ^ (((k >> 2) & 7) << 2)));
            const float* bb = Bs + k * 160 + tx * 10;
            float bv[10];
            float2 t0 = *(const float2*)(bb + 0);
            float2 t1 = *(const float2*)(bb + 2);
            float2 t2 = *(const float2*)(bb + 4);
            float2 t3 = *(const float2*)(bb + 6);
            float2 t4 = *(const float2*)(bb + 8);
            bv[0] = t0.x; bv[1] = t0.y; bv[2] = t1.x; bv[3] = t1.y; bv[4] = t2.x;
            bv[5] = t2.y; bv[6] = t3.x; bv[7] = t3.y; bv[8] = t4.x; bv[9] = t4.y;
#pragma unroll
            for (int j = 0; j < 10; j++) {
                acc[0][j] += a.x * bv[j];
                acc[1][j] += a.y * bv[j];
                acc[2][j] += a.z * bv[j];
                acc[3][j] += a.w * bv[j];
            }
        }
        __syncthreads();
    }

    float* outp = (n0 < HC) ? g_xl : g_xr;
#pragma unroll
    for (int r = 0; r < 4; r++) {
        int grow = row0 + ty * 4 + r;
        if (grow < N_NODES) {
#pragma unroll
            for (int j = 0; j < 10; j++) {
                int cl = tx * 10 + j;
                outp[(size_t)grow * HC + ncol0 + cl] = acc[r][j] + biasp[ncol0 + cl];
            }
        }
    }
}

// ---------------- bf16 tensor-core score GEMM + fused attention epilogue ----------
// MODE 1: A = edge_attr [E x 128] @ W_e ; MODE 2: A = sumattr/cnt [N x 128] @ W_e
// A (bf16 pair-packed, full K=128) resident in smem: ONE exposed DRAM latency
// per block instead of four. B (W_e, L2-resident) staged in 4 chunks of K=32.
// mma.m16n8k16.bf16: half the MMA + fragment-LDS count of the tf32 k8 version.
// Pair-pack orientation is self-consistent between A and B (any lo/hi swap
// permutes k within pairs identically on both sides -> same dot product).

__device__ __forceinline__ uint32_t pack_bf16x2(float lo, float hi) {
    uint32_t r;
    asm("cvt.rn.bf16x2.f32 %0, %1, %2;" : "=r"(r) : "f"(hi), "f"(lo));
    return r;
}

#define MMA_BF16(c, a, b)                                                      \
    asm volatile(                                                              \
        "mma.sync.aligned.m16n8k16.row.col.f32.bf16.bf16.f32 "                 \
        "{%0,%1,%2,%3}, {%4,%5,%6,%7}, {%8,%9}, {%0,%1,%2,%3};"                \
        : "+f"(c[0]), "+f"(c[1]), "+f"(c[2]), "+f"(c[3])                       \
        : "r"(a[0]), "r"(a[1]), "r"(a[2]), "r"(a[3]), "r"(b[0]), "r"(b[1]))

#define ASTRIDE16 68     // A: [64 rows][64 k-pairs + 4 pad]; frag banks 4g+tg (clean)
#define BSTRIDE16 168    // B: [16 k-pairs][160 n + 8 pad]; frag banks 8tg+g (clean)

template <int MODE>
__global__ __launch_bounds__(256, 2)
void score_gemm(const float* __restrict__ Asrc, const float* __restrict__ We,
                const float* __restrict__ att, const int* __restrict__ ei) {
    __shared__ float sm[10560];           // As16 4352 + Bs16 2688 = 7040; zsm[64][165]
    __shared__ int s_src[64], s_dst[64];
    __shared__ float s_rinv[64];
    uint32_t* As16 = (uint32_t*)sm;            // [64][68] bf16x2
    uint32_t* Bs16 = (uint32_t*)sm + 4352;     // [16][168] bf16x2

    const int tid = threadIdx.x;
    const int row0 = blockIdx.x * 64;
    const int n0 = blockIdx.y * 160;
    const int warp = tid >> 5, lane = tid & 31;
    const int g = lane >> 2, tg = lane & 3;
    const int wm = warp >> 2, wn = warp & 3;

    if (MODE == 1) {
        if (tid < 64) {
            s_src[tid] = ei[row0 + tid];
            s_dst[tid] = ei[N_EDGES + row0 + tid];
        }
    } else {
        if (tid < 64) {
            int node = row0 + tid;
            int ok = (node < N_NODES);
            int c = ok ? g_cnt[node] : 1;
            if (c < 1) c = 1;
            s_rinv[tid] = 1.0f / (float)c;
            s_src[tid] = ok ? node : 0;
            s_dst[tid] = s_src[tid];
        }
    }
    __syncthreads();                      // s_rinv visible for MODE 2 A staging

    // ---- stage ALL of A (64 rows x K=128) as bf16 pairs, ONCE ----
#pragma unroll
    for (int j = 0; j < 8; j++) {
        int i = tid + j * 256;            // 0..2047 float4 slots
        int r = i >> 5;                   // row 0..63
        int c4 = i & 31;                  // float4 index along K
        float4 v;
        if (MODE == 1) {
            v = *(const float4*)(Asrc + (size_t)(row0 + r) * FIN + c4 * 4);
        } else {
            int grow = row0 + r;
            if (grow < N_NODES) {
                v = *(const float4*)((const float*)g_sumattr4 + (size_t)grow * FIN + c4 * 4);
                float s = s_rinv[r];
                v.x *= s; v.y *= s; v.z *= s; v.w *= s;
            } else {
                v = make_float4(0.f, 0.f, 0.f, 0.f);
            }
        }
        uint2 u;
        u.x = pack_bf16x2(v.x, v.y);
        u.y = pack_bf16x2(v.z, v.w);
        *(uint2*)(As16 + r * ASTRIDE16 + c4 * 2) = u;
    }

    float acc[2][5][4];
#pragma unroll
    for (int mi = 0; mi < 2; mi++)
#pragma unroll
        for (int nt = 0; nt < 5; nt++)
#pragma unroll
            for (int q = 0; q < 4; q++) acc[mi][nt][q] = 0.f;

    for (int kc = 0; kc < FIN; kc += 32) {
        __syncthreads();                  // prev chunk's B fully consumed
        // ---- stage B chunk [K=32 -> 16 pairs][160 n] (L2-resident W_e) ----
#pragma unroll
        for (int j = 0; j < 3; j++) {
            int i = tid + j * 256;        // 0..639 uint4 slots
            if (i < 640) {
                int p = i / 40;           // k-pair 0..15
                int n4 = i % 40;
                const float* bp = We + (size_t)(kc + 2 * p) * HC + n0 + n4 * 4;
                float4 r0 = *(const float4*)bp;
                float4 r1 = *(const float4*)(bp + HC);
                uint4 u;
                u.x = pack_bf16x2(r0.x, r1.x);
                u.y = pack_bf16x2(r0.y, r1.y);
                u.z = pack_bf16x2(r0.z, r1.z);
                u.w = pack_bf16x2(r0.w, r1.w);
                *(uint4*)(Bs16 + p * BSTRIDE16 + n4 * 4) = u;
            }
        }
        __syncthreads();

        const int pbase = kc >> 1;        // A pair base for this chunk
#pragma unroll
        for (int s = 0; s < 2; s++) {     // two k16 steps per chunk
            uint32_t a[2][4], b[5][2];
#pragma unroll
            for (int mi = 0; mi < 2; mi++) {
                int m = wm * 32 + mi * 16;
                a[mi][0] = As16[(m + g) * ASTRIDE16 + pbase + s * 8 + tg];
                a[mi][1] = As16[(m + g + 8) * ASTRIDE16 + pbase + s * 8 + tg];
                a[mi][2] = As16[(m + g) * ASTRIDE16 + pbase + s * 8 + tg + 4];
                a[mi][3] = As16[(m + g + 8) * ASTRIDE16 + pbase + s * 8 + tg + 4];
            }
#pragma unroll
            for (int nt = 0; nt < 5; nt++) {
                int n = wn * 40 + nt * 8 + g;
                b[nt][0] = Bs16[(s * 8 + tg) * BSTRIDE16 + n];
                b[nt][1] = Bs16[(s * 8 + tg + 4) * BSTRIDE16 + n];
            }
#pragma unroll
            for (int mi = 0; mi < 2; mi++)
#pragma unroll
                for (int nt = 0; nt < 5; nt++)
                    MMA_BF16(acc[mi][nt], a[mi], b[nt]);
        }
    }
    __syncthreads();

    // --- epilogue: z = leaky(e + xl[src] + xr[dst]); stage z*att into zsm (stride 165)
    float* zsm = sm;
#pragma unroll
    for (int mi = 0; mi < 2; mi++) {
        int r0 = wm * 32 + mi * 16 + g;        // rows r0 and r0+8
        int s0 = s_src[r0], d0 = s_dst[r0];
        int s1 = s_src[r0 + 8], d1 = s_dst[r0 + 8];
        const float* xl0 = g_xl + (size_t)s0 * HC + n0;
        const float* xr0 = g_xr + (size_t)d0 * HC + n0;
        const float* xl1 = g_xl + (size_t)s1 * HC + n0;
        const float* xr1 = g_xr + (size_t)d1 * HC + n0;
#pragma unroll
        for (int nt = 0; nt < 5; nt++) {
            int cB = wn * 40 + nt * 8 + 2 * tg;
            float at0 = att[n0 + cB], at1 = att[n0 + cB + 1];
            float z;
            z = acc[mi][nt][0] + xl0[cB] + xr0[cB];
            z = (z > 0.f) ? z : NEG_SLOPE * z;
            zsm[r0 * 165 + cB] = z * at0;
            z = acc[mi][nt][1] + xl0[cB + 1] + xr0[cB + 1];
            z = (z > 0.f) ? z : NEG_SLOPE * z;
            zsm[r0 * 165 + cB + 1] = z * at1;
            z = acc[mi][nt][2] + xl1[cB] + xr1[cB];
            z = (z > 0.f) ? z : NEG_SLOPE * z;
            zsm[(r0 + 8) * 165 + cB] = z * at0;
            z = acc[mi][nt][3] + xl1[cB + 1] + xr1[cB + 1];
            z = (z > 0.f) ? z : NEG_SLOPE * z;
            zsm[(r0 + 8) * 165 + cB + 1] = z * at1;
        }
    }
    __syncthreads();

    // --- per (row, head) sum over 32 channels -> p = exp(score); denom atomics
    for (int task = tid; task < 320; task += 256) {
        int row = task & 63;
        int hh = task >> 6;                    // 0..4 (this n-half covers 5 heads)
        float s = 0.f;
#pragma unroll
        for (int i = 0; i < 32; i++) s += zsm[row * 165 + hh * 32 + i];
        float p = __expf(s);
        int hg = blockIdx.y * 5 + hh;
        if (MODE == 1) {
            int e = row0 + row;
            g_p[(size_t)e * NHEAD + hg] = p;
            atomicAdd(&g_denom[(size_t)s_dst[row] * NHEAD + hg], p);
        } else {
            int node = row0 + row;
            if (node < N_NODES) {
                g_pself[(size_t)node * NHEAD + hg] = p;
                atomicAdd(&g_denom[(size_t)node * NHEAD + hg], p);
            }
        }
    }
}

// ---------------- edge message pass: acc[dst] += sum_h alpha_h * xl[src,h,:] ----------------
__global__ void edge_msg(const int* __restrict__ ei) {
    int gwarp = (blockIdx.x * blockDim.x + threadIdx.x) >> 5;
    int lane = threadIdx.x & 31;
    if (gwarp >= N_EDGES) return;
    int src = ei[gwarp];
    int dst = ei[N_EDGES + gwarp];
    float alpha = 0.f;
    if (lane < NHEAD)
        alpha = g_p[(size_t)gwarp * NHEAD + lane] / g_denom[(size_t)dst * NHEAD + lane];
    const float* xl = g_xl + (size_t)src * HC;
    float m = 0.f;
#pragma unroll
    for (int h = 0; h < NHEAD; h++) {
        float a = __shfl_sync(0xffffffff, alpha, h);
        m += a * xl[h * CH + lane];
    }
    atomicAdd(&g_acc[(size_t)dst * CH + lane], m);
}

// ---------------- node finalize + global mean pool (smem-staged atomics) ----------------
__global__ void finalize_pool(const int* __restrict__ batch, const float* __restrict__ bias_gat) {
    __shared__ float s_gsum[B_GRAPHS * CH];
    __shared__ int s_gcnt[B_GRAPHS];
    int tid = threadIdx.x;
    for (int i = tid; i < B_GRAPHS * CH; i += 256) s_gsum[i] = 0.f;
    if (tid < B_GRAPHS) s_gcnt[tid] = 0;
    __syncthreads();

    int warp = tid >> 5, lane = tid & 31;
    for (int u = 0; u < 8; u++) {
        int node = blockIdx.x * 64 + warp * 8 + u;
        if (node < N_NODES) {
            int b = batch[node];
            float a = 0.f;
            if (lane < NHEAD)
                a = g_pself[(size_t)node * NHEAD + lane] / g_denom[(size_t)node * NHEAD + lane];
            const float* xl = g_xl + (size_t)node * HC;
            float selfm = 0.f;
#pragma unroll
            for (int h = 0; h < NHEAD; h++) {
                float ah = __shfl_sync(0xffffffff, a, h);
                selfm += ah * xl[h * CH + lane];
            }
            float v = (g_acc[(size_t)node * CH + lane] + selfm) * (1.0f / NHEAD) + bias_gat[lane];
            v = fmaxf(v, 0.f);
            atomicAdd(&s_gsum[b * CH + lane], v);
            if (lane == 0) atomicAdd(&s_gcnt[b], 1);
        }
    }
    __syncthreads();
    for (int i = tid; i < B_GRAPHS * CH; i += 256)
        if (s_gsum[i] != 0.f) atomicAdd(&g_gsum[i], s_gsum[i]);
    if (tid < B_GRAPHS && s_gcnt[tid] != 0) atomicAdd(&g_gcnt[tid], s_gcnt[tid]);
}

// ---------------- head: out[b, o] = (gsum[b]/cnt[b]) @ W_head + b_head ----------------
__global__ void head_kernel(const float* __restrict__ Wh, const float* __restrict__ bh,
                            float* __restrict__ out) {
    int t = threadIdx.x;
    if (t < B_GRAPHS * 2) {
        int b = t >> 1, o = t & 1;
        int c = g_gcnt[b]; if (c < 1) c = 1;
        float inv = 1.0f / (float)c;
        float s = 0.f;
#pragma unroll
        for (int k = 0; k < CH; k++) s += (g_gsum[b * CH + k] * inv) * Wh[k * 2 + o];
        out[t] = s + bh[o];
    }
}

extern "C" void kernel_launch(void* const* d_in, const int* in_sizes, int n_in,
                              void* d_out, int out_size) {
    const float* x        = (const float*)d_in[0];
    const int*   ei       = (const int*)d_in[1];
    const float* ea       = (const float*)d_in[2];
    const int*   batch    = (const int*)d_in[3];
    const float* bn_g     = (const float*)d_in[4];
    const float* bn_b     = (const float*)d_in[5];
    const float* bn_m     = (const float*)d_in[6];
    const float* bn_v     = (const float*)d_in[7];
    const float* Wl       = (const float*)d_in[8];
    const float* bl       = (const float*)d_in[9];
    const float* Wr       = (const float*)d_in[10];
    const float* br       = (const float*)d_in[11];
    const float* We       = (const float*)d_in[12];
    const float* att      = (const float*)d_in[13];
    const float* bias_gat = (const float*)d_in[14];
    const float* Wh       = (const float*)d_in[15];
    const float* bh       = (const float*)d_in[16];
    float* out = (float*)d_out;

    zero_bufs<<<512, 256>>>();
    scatter_attr<<<(N_EDGES * 32) / 256, 256>>>(ea, ei);
    // x_l / x_r : exact fp32 (message values)
    xlr_kernel<<<dim3(313, 4), 256>>>(x, Wl, Wr, bl, br, bn_g, bn_b, bn_m, bn_v);
    // self-loop scores (bf16 tensor cores)
    score_gemm<2><<<dim3(313, 2), 256>>>(nullptr, We, att, ei);
    // edge scores (26-GFLOP GEMM, bf16 tensor cores, A-resident, fused epilogue)
    score_gemm<1><<<dim3(5000, 2), 256>>>(ea, We, att, ei);
    edge_msg<<<(N_EDGES * 32) / 256, 256>>>(ei);
    finalize_pool<<<313, 256>>>(batch, bias_gat);
    head_kernel<<<1, 128>>>(Wh, bh, out);
}

// round 16
// speedup vs baseline: 1.2083x; 1.0200x over previous
#include <cuda_runtime.h>
#include <math.h>
#include <stdint.h>

#define N_NODES 20000
#define N_EDGES 320000
#define FIN 128
#define HC 320
#define NHEAD 10
#define CH 32
#define B_GRAPHS 64
#define NEG_SLOPE 0.2f
#define BN_EPS 1e-5f

// ---------------- scratch (device globals; no allocs allowed) ----------------
__device__ float  g_xl[(size_t)N_NODES * HC];        // 25.6 MB
__device__ float  g_xr[(size_t)N_NODES * HC];        // 25.6 MB
__device__ float4 g_sumattr4[(size_t)N_NODES * FIN / 4];  // 10.24 MB
__device__ int    g_cnt[N_NODES];
__device__ float  g_p[(size_t)N_EDGES * NHEAD];      // 12.8 MB  exp(score) per edge
__device__ float  g_pself[(size_t)N_NODES * NHEAD];
__device__ float  g_denom[(size_t)N_NODES * NHEAD];
__device__ float  g_acc[(size_t)N_NODES * CH];
__device__ float  g_gsum[B_GRAPHS * CH];
__device__ int    g_gcnt[B_GRAPHS];

// ---------------- zero scratch ----------------
__global__ void zero_bufs() {
    int i0 = blockIdx.x * blockDim.x + threadIdx.x;
    int stride = gridDim.x * blockDim.x;
    float4 z4 = make_float4(0.f, 0.f, 0.f, 0.f);
    for (int i = i0; i < N_NODES * FIN / 4; i += stride) g_sumattr4[i] = z4;
    for (int i = i0; i < N_NODES; i += stride) g_cnt[i] = 0;
    for (int i = i0; i < N_NODES * NHEAD; i += stride) g_denom[i] = 0.f;
    for (int i = i0; i < N_NODES * CH; i += stride) g_acc[i] = 0.f;
    for (int i = i0; i < B_GRAPHS * CH; i += stride) g_gsum[i] = 0.f;
    for (int i = i0; i < B_GRAPHS; i += stride) g_gcnt[i] = 0;
}

// ---------------- segment-sum of edge_attr by dst (vector red) ----------------
__device__ __forceinline__ void red_add_f4(float4* addr, float4 v) {
    asm volatile("red.global.add.v4.f32 [%0], {%1,%2,%3,%4};"
                 :: "l"(addr), "f"(v.x), "f"(v.y), "f"(v.z), "f"(v.w) : "memory");
}

__global__ void scatter_attr(const float* __restrict__ ea, const int* __restrict__ ei) {
    int t = blockIdx.x * blockDim.x + threadIdx.x;
    int edge = t >> 5;
    int lane = t & 31;
    if (edge >= N_EDGES) return;
    int dst = ei[N_EDGES + edge];
    float4 v = ((const float4*)(ea + (size_t)edge * FIN))[lane];
    red_add_f4(&g_sumattr4[(size_t)dst * (FIN / 4) + lane], v);
    if (lane == 0) atomicAdd(&g_cnt[dst], 1);
}

// ---------------- x_l / x_r FFMA GEMM (exact fp32: these are the message values) ---
// A = BN(x) [N x 128], B = [W_l | W_r] (640 virtual cols), store x_l / x_r
__global__ __launch_bounds__(256)
void xlr_kernel(const float* __restrict__ Asrc,
                const float* __restrict__ Wl, const float* __restrict__ Wr,
                const float* __restrict__ bl, const float* __restrict__ br,
                const float* __restrict__ bn_g, const float* __restrict__ bn_b,
                const float* __restrict__ bn_m, const float* __restrict__ bn_v) {
    __shared__ float smem[10304];
    __shared__ float s_bnsc[FIN], s_bnsh[FIN];
    float* As = smem;            // 2048 floats, swizzled transposed
    float* Bs = smem + 2048;     // 5120 floats

    const int tid = threadIdx.x;
    const int row0 = blockIdx.x * 64;
    const int n0 = blockIdx.y * 160;

    const float* Bptr;
    const float* biasp;
    int ncol0;
    if (n0 < HC) { Bptr = Wl; biasp = bl; ncol0 = n0; }
    else         { Bptr = Wr; biasp = br; ncol0 = n0 - HC; }

    if (tid < FIN) {
        float sc = bn_g[tid] * rsqrtf(bn_v[tid] + BN_EPS);
        s_bnsc[tid] = sc;
        s_bnsh[tid] = bn_b[tid] - bn_m[tid] * sc;
    }
    __syncthreads();

    float acc[4][10];
#pragma unroll
    for (int r = 0; r < 4; r++)
#pragma unroll
        for (int j = 0; j < 10; j++) acc[r][j] = 0.f;

    const int ty = tid >> 4;
    const int tx = tid & 15;

    for (int kc = 0; kc < FIN; kc += 32) {
#pragma unroll
        for (int j = 0; j < 2; j++) {
            int i = tid + j * 256;
            int r = i >> 3;
            int c4 = i & 7;
            int grow = row0 + r;
            float4 v = make_float4(0.f, 0.f, 0.f, 0.f);
            if (grow < N_NODES) {
                v = *(const float4*)(Asrc + (size_t)grow * FIN + kc + c4 * 4);
                int kb = kc + c4 * 4;
                v.x = v.x * s_bnsc[kb + 0] + s_bnsh[kb + 0];
                v.y = v.y * s_bnsc[kb + 1] + s_bnsh[kb + 1];
                v.z = v.z * s_bnsc[kb + 2] + s_bnsh[kb + 2];
                v.w = v.w * s_bnsc[kb + 3] + s_bnsh[kb + 3];
            }
            int m2 = r ^ (c4 << 2);
            As[(c4 * 4 + 0) * 64 + m2] = v.x;
            As[(c4 * 4 + 1) * 64 + m2] = v.y;
            As[(c4 * 4 + 2) * 64 + m2] = v.z;
            As[(c4 * 4 + 3) * 64 + m2] = v.w;
        }
#pragma unroll
        for (int j = 0; j < 5; j++) {
            int i = tid + j * 256;
            int kk = i / 40;
            int n4 = i % 40;
            float4 v = *(const float4*)(Bptr + (size_t)(kc + kk) * HC + ncol0 + n4 * 4);
            *(float4*)(Bs + kk * 160 + n4 * 4) = v;
        }
        __syncthreads();

#pragma unroll 8
        for (int k = 0; k < 32; k++) {
            float4 a = *(const float4*)(As + k * 64 + ((ty * 4) ^ (((k >> 2) & 7) << 2)));
            const float* bb = Bs + k * 160 + tx * 10;
            float bv[10];
            float2 t0 = *(const float2*)(bb + 0);
            float2 t1 = *(const float2*)(bb + 2);
            float2 t2 = *(const float2*)(bb + 4);
            float2 t3 = *(const float2*)(bb + 6);
            float2 t4 = *(const float2*)(bb + 8);
            bv[0] = t0.x; bv[1] = t0.y; bv[2] = t1.x; bv[3] = t1.y; bv[4] = t2.x;
            bv[5] = t2.y; bv[6] = t3.x; bv[7] = t3.y; bv[8] = t4.x; bv[9] = t4.y;
#pragma unroll
            for (int j = 0; j < 10; j++) {
                acc[0][j] += a.x * bv[j];
                acc[1][j] += a.y * bv[j];
                acc[2][j] += a.z * bv[j];
                acc[3][j] += a.w * bv[j];
            }
        }
        __syncthreads();
    }

    float* outp = (n0 < HC) ? g_xl : g_xr;
#pragma unroll
    for (int r = 0; r < 4; r++) {
        int grow = row0 + ty * 4 + r;
        if (grow < N_NODES) {
#pragma unroll
            for (int j = 0; j < 10; j++) {
                int cl = tx * 10 + j;
                outp[(size_t)grow * HC + ncol0 + cl] = acc[r][j] + biasp[ncol0 + cl];
            }
        }
    }
}

// ---------------- bf16 tensor-core score GEMM + fused attention epilogue ----------
// MODE 1: A = edge_attr [E x 128] @ W_e ; MODE 2: A = sumattr/cnt [N x 128] @ W_e
// A (bf16 pair-packed, full K=128) resident in smem. B (W_e, L2-resident)
// staged in TWO chunks of K=64 (was four of K=32): halves barrier count and
// exposed B-latency rounds. mma.m16n8k16.bf16.

__device__ __forceinline__ uint32_t pack_bf16x2(float lo, float hi) {
    uint32_t r;
    asm("cvt.rn.bf16x2.f32 %0, %1, %2;" : "=r"(r) : "f"(hi), "f"(lo));
    return r;
}

#define MMA_BF16(c, a, b)                                                      \
    asm volatile(                                                              \
        "mma.sync.aligned.m16n8k16.row.col.f32.bf16.bf16.f32 "                 \
        "{%0,%1,%2,%3}, {%4,%5,%6,%7}, {%8,%9}, {%0,%1,%2,%3};"                \
        : "+f"(c[0]), "+f"(c[1]), "+f"(c[2]), "+f"(c[3])                       \
        : "r"(a[0]), "r"(a[1]), "r"(a[2]), "r"(a[3]), "r"(b[0]), "r"(b[1]))

#define ASTRIDE16 68     // A: [64 rows][64 k-pairs + 4 pad]; frag banks 4g+tg (clean)
#define BSTRIDE16 168    // B: [32 k-pairs][160 n + 8 pad]; frag banks 8tg+g (clean)

template <int MODE>
__global__ __launch_bounds__(256, 2)
void score_gemm(const float* __restrict__ Asrc, const float* __restrict__ We,
                const float* __restrict__ att, const int* __restrict__ ei) {
    __shared__ float sm[10560];           // As16 4352u + Bs16 5376u = 9728u (38912B); zsm[64][165]
    __shared__ int s_src[64], s_dst[64];
    __shared__ float s_rinv[64];
    uint32_t* As16 = (uint32_t*)sm;            // [64][68] bf16x2
    uint32_t* Bs16 = (uint32_t*)sm + 4352;     // [32][168] bf16x2

    const int tid = threadIdx.x;
    const int row0 = blockIdx.x * 64;
    const int n0 = blockIdx.y * 160;
    const int warp = tid >> 5, lane = tid & 31;
    const int g = lane >> 2, tg = lane & 3;
    const int wm = warp >> 2, wn = warp & 3;

    if (MODE == 1) {
        if (tid < 64) {
            s_src[tid] = ei[row0 + tid];
            s_dst[tid] = ei[N_EDGES + row0 + tid];
        }
    } else {
        if (tid < 64) {
            int node = row0 + tid;
            int ok = (node < N_NODES);
            int c = ok ? g_cnt[node] : 1;
            if (c < 1) c = 1;
            s_rinv[tid] = 1.0f / (float)c;
            s_src[tid] = ok ? node : 0;
            s_dst[tid] = s_src[tid];
        }
    }
    __syncthreads();                      // s_rinv visible for MODE 2 A staging

    // ---- stage ALL of A (64 rows x K=128) as bf16 pairs, ONCE ----
#pragma unroll
    for (int j = 0; j < 8; j++) {
        int i = tid + j * 256;            // 0..2047 float4 slots
        int r = i >> 5;                   // row 0..63
        int c4 = i & 31;                  // float4 index along K
        float4 v;
        if (MODE == 1) {
            v = *(const float4*)(Asrc + (size_t)(row0 + r) * FIN + c4 * 4);
        } else {
            int grow = row0 + r;
            if (grow < N_NODES) {
                v = *(const float4*)((const float*)g_sumattr4 + (size_t)grow * FIN + c4 * 4);
                float s = s_rinv[r];
                v.x *= s; v.y *= s; v.z *= s; v.w *= s;
            } else {
                v = make_float4(0.f, 0.f, 0.f, 0.f);
            }
        }
        uint2 u;
        u.x = pack_bf16x2(v.x, v.y);
        u.y = pack_bf16x2(v.z, v.w);
        *(uint2*)(As16 + r * ASTRIDE16 + c4 * 2) = u;
    }

    float acc[2][5][4];
#pragma unroll
    for (int mi = 0; mi < 2; mi++)
#pragma unroll
        for (int nt = 0; nt < 5; nt++)
#pragma unroll
            for (int q = 0; q < 4; q++) acc[mi][nt][q] = 0.f;

    for (int kc = 0; kc < FIN; kc += 64) {
        __syncthreads();                  // prev chunk's B fully consumed
        // ---- stage B chunk [K=64 -> 32 pairs][160 n] (L2-resident W_e) ----
#pragma unroll
        for (int j = 0; j < 5; j++) {
            int i = tid + j * 256;        // 0..1279 uint4 slots
            if (i < 1280) {
                int p = i / 40;           // k-pair 0..31
                int n4 = i % 40;
                const float* bp = We + (size_t)(kc + 2 * p) * HC + n0 + n4 * 4;
                float4 r0 = *(const float4*)bp;
                float4 r1 = *(const float4*)(bp + HC);
                uint4 u;
                u.x = pack_bf16x2(r0.x, r1.x);
                u.y = pack_bf16x2(r0.y, r1.y);
                u.z = pack_bf16x2(r0.z, r1.z);
                u.w = pack_bf16x2(r0.w, r1.w);
                *(uint4*)(Bs16 + p * BSTRIDE16 + n4 * 4) = u;
            }
        }
        __syncthreads();

        const int pbase = kc >> 1;        // A pair base for this chunk
#pragma unroll
        for (int s = 0; s < 4; s++) {     // four k16 steps per chunk
            uint32_t a[2][4], b[5][2];
#pragma unroll
            for (int mi = 0; mi < 2; mi++) {
                int m = wm * 32 + mi * 16;
                a[mi][0] = As16[(m + g) * ASTRIDE16 + pbase + s * 8 + tg];
                a[mi][1] = As16[(m + g + 8) * ASTRIDE16 + pbase + s * 8 + tg];
                a[mi][2] = As16[(m + g) * ASTRIDE16 + pbase + s * 8 + tg + 4];
                a[mi][3] = As16[(m + g + 8) * ASTRIDE16 + pbase + s * 8 + tg + 4];
            }
#pragma unroll
            for (int nt = 0; nt < 5; nt++) {
                int n = wn * 40 + nt * 8 + g;
                b[nt][0] = Bs16[(s * 8 + tg) * BSTRIDE16 + n];
                b[nt][1] = Bs16[(s * 8 + tg + 4) * BSTRIDE16 + n];
            }
#pragma unroll
            for (int mi = 0; mi < 2; mi++)
#pragma unroll
                for (int nt = 0; nt < 5; nt++)
                    MMA_BF16(acc[mi][nt], a[mi], b[nt]);
        }
    }
    __syncthreads();

    // --- epilogue: z = leaky(e + xl[src] + xr[dst]); stage z*att into zsm (stride 165)
    float* zsm = sm;
#pragma unroll
    for (int mi = 0; mi < 2; mi++) {
        int r0 = wm * 32 + mi * 16 + g;        // rows r0 and r0+8
        int s0 = s_src[r0], d0 = s_dst[r0];
        int s1 = s_src[r0 + 8], d1 = s_dst[r0 + 8];
        const float* xl0 = g_xl + (size_t)s0 * HC + n0;
        const float* xr0 = g_xr + (size_t)d0 * HC + n0;
        const float* xl1 = g_xl + (size_t)s1 * HC + n0;
        const float* xr1 = g_xr + (size_t)d1 * HC + n0;
#pragma unroll
        for (int nt = 0; nt < 5; nt++) {
            int cB = wn * 40 + nt * 8 + 2 * tg;
            float at0 = att[n0 + cB], at1 = att[n0 + cB + 1];
            float z;
            z = acc[mi][nt][0] + xl0[cB] + xr0[cB];
            z = (z > 0.f) ? z : NEG_SLOPE * z;
            zsm[r0 * 165 + cB] = z * at0;
            z = acc[mi][nt][1] + xl0[cB + 1] + xr0[cB + 1];
            z = (z > 0.f) ? z : NEG_SLOPE * z;
            zsm[r0 * 165 + cB + 1] = z * at1;
            z = acc[mi][nt][2] + xl1[cB] + xr1[cB];
            z = (z > 0.f) ? z : NEG_SLOPE * z;
            zsm[(r0 + 8) * 165 + cB] = z * at0;
            z = acc[mi][nt][3] + xl1[cB + 1] + xr1[cB + 1];
            z = (z > 0.f) ? z : NEG_SLOPE * z;
            zsm[(r0 + 8) * 165 + cB + 1] = z * at1;
        }
    }
    __syncthreads();

    // --- per (row, head) sum over 32 channels -> p = exp(score); denom atomics
    for (int task = tid; task < 320; task += 256) {
        int row = task & 63;
        int hh = task >> 6;                    // 0..4 (this n-half covers 5 heads)
        float s = 0.f;
#pragma unroll
        for (int i = 0; i < 32; i++) s += zsm[row * 165 + hh * 32 + i];
        float p = __expf(s);
        int hg = blockIdx.y * 5 + hh;
        if (MODE == 1) {
            int e = row0 + row;
            g_p[(size_t)e * NHEAD + hg] = p;
            atomicAdd(&g_denom[(size_t)s_dst[row] * NHEAD + hg], p);
        } else {
            int node = row0 + row;
            if (node < N_NODES) {
                g_pself[(size_t)node * NHEAD + hg] = p;
                atomicAdd(&g_denom[(size_t)node * NHEAD + hg], p);
            }
        }
    }
}

// ---------------- edge message pass: acc[dst] += sum_h alpha_h * xl[src,h,:] ----------------
__global__ void edge_msg(const int* __restrict__ ei) {
    int gwarp = (blockIdx.x * blockDim.x + threadIdx.x) >> 5;
    int lane = threadIdx.x & 31;
    if (gwarp >= N_EDGES) return;
    int src = ei[gwarp];
    int dst = ei[N_EDGES + gwarp];
    float alpha = 0.f;
    if (lane < NHEAD)
        alpha = g_p[(size_t)gwarp * NHEAD + lane] / g_denom[(size_t)dst * NHEAD + lane];
    const float* xl = g_xl + (size_t)src * HC;
    float m = 0.f;
#pragma unroll
    for (int h = 0; h < NHEAD; h++) {
        float a = __shfl_sync(0xffffffff, alpha, h);
        m += a * xl[h * CH + lane];
    }
    atomicAdd(&g_acc[(size_t)dst * CH + lane], m);
}

// ---------------- node finalize + global mean pool (smem-staged atomics) ----------------
__global__ void finalize_pool(const int* __restrict__ batch, const float* __restrict__ bias_gat) {
    __shared__ float s_gsum[B_GRAPHS * CH];
    __shared__ int s_gcnt[B_GRAPHS];
    int tid = threadIdx.x;
    for (int i = tid; i < B_GRAPHS * CH; i += 256) s_gsum[i] = 0.f;
    if (tid < B_GRAPHS) s_gcnt[tid] = 0;
    __syncthreads();

    int warp = tid >> 5, lane = tid & 31;
    for (int u = 0; u < 8; u++) {
        int node = blockIdx.x * 64 + warp * 8 + u;
        if (node < N_NODES) {
            int b = batch[node];
            float a = 0.f;
            if (lane < NHEAD)
                a = g_pself[(size_t)node * NHEAD + lane] / g_denom[(size_t)node * NHEAD + lane];
            const float* xl = g_xl + (size_t)node * HC;
            float selfm = 0.f;
#pragma unroll
            for (int h = 0; h < NHEAD; h++) {
                float ah = __shfl_sync(0xffffffff, a, h);
                selfm += ah * xl[h * CH + lane];
            }
            float v = (g_acc[(size_t)node * CH + lane] + selfm) * (1.0f / NHEAD) + bias_gat[lane];
            v = fmaxf(v, 0.f);
            atomicAdd(&s_gsum[b * CH + lane], v);
            if (lane == 0) atomicAdd(&s_gcnt[b], 1);
        }
    }
    __syncthreads();
    for (int i = tid; i < B_GRAPHS * CH; i += 256)
        if (s_gsum[i] != 0.f) atomicAdd(&g_gsum[i], s_gsum[i]);
    if (tid < B_GRAPHS && s_gcnt[tid] != 0) atomicAdd(&g_gcnt[tid], s_gcnt[tid]);
}

// ---------------- head: out[b, o] = (gsum[b]/cnt[b]) @ W_head + b_head ----------------
__global__ void head_kernel(const float* __restrict__ Wh, const float* __restrict__ bh,
                            float* __restrict__ out) {
    int t = threadIdx.x;
    if (t < B_GRAPHS * 2) {
        int b = t >> 1, o = t & 1;
        int c = g_gcnt[b]; if (c < 1) c = 1;
        float inv = 1.0f / (float)c;
        float s = 0.f;
#pragma unroll
        for (int k = 0; k < CH; k++) s += (g_gsum[b * CH + k] * inv) * Wh[k * 2 + o];
        out[t] = s + bh[o];
    }
}

extern "C" void kernel_launch(void* const* d_in, const int* in_sizes, int n_in,
                              void* d_out, int out_size) {
    const float* x        = (const float*)d_in[0];
    const int*   ei       = (const int*)d_in[1];
    const float* ea       = (const float*)d_in[2];
    const int*   batch    = (const int*)d_in[3];
    const float* bn_g     = (const float*)d_in[4];
    const float* bn_b     = (const float*)d_in[5];
    const float* bn_m     = (const float*)d_in[6];
    const float* bn_v     = (const float*)d_in[7];
    const float* Wl       = (const float*)d_in[8];
    const float* bl       = (const float*)d_in[9];
    const float* Wr       = (const float*)d_in[10];
    const float* br       = (const float*)d_in[11];
    const float* We       = (const float*)d_in[12];
    const float* att      = (const float*)d_in[13];
    const float* bias_gat = (const float*)d_in[14];
    const float* Wh       = (const float*)d_in[15];
    const float* bh       = (const float*)d_in[16];
    float* out = (float*)d_out;

    zero_bufs<<<512, 256>>>();
    scatter_attr<<<(N_EDGES * 32) / 256, 256>>>(ea, ei);
    // x_l / x_r : exact fp32 (message values)
    xlr_kernel<<<dim3(313, 4), 256>>>(x, Wl, Wr, bl, br, bn_g, bn_b, bn_m, bn_v);
    // self-loop scores (bf16 tensor cores)
    score_gemm<2><<<dim3(313, 2), 256>>>(nullptr, We, att, ei);
    // edge scores (26-GFLOP GEMM, bf16 tensor cores, A-resident, K=64 B chunks)
    score_gemm<1><<<dim3(5000, 2), 256>>>(ea, We, att, ei);
    edge_msg<<<(N_EDGES * 32) / 256, 256>>>(ei);
    finalize_pool<<<313, 256>>>(batch, bias_gat);
    head_kernel<<<1, 128>>>(Wh, bh, out);
}

// round 17
// speedup vs baseline: 1.3566x; 1.1228x over previous
#include <cuda_runtime.h>
#include <math.h>
#include <stdint.h>

#define N_NODES 20000
#define N_EDGES 320000
#define FIN 128
#define HC 320
#define NHEAD 10
#define CH 32
#define B_GRAPHS 64
#define NEG_SLOPE 0.2f
#define BN_EPS 1e-5f

// ---------------- scratch (device globals; no allocs allowed) ----------------
__device__ float  g_xl[(size_t)N_NODES * HC];        // 25.6 MB
__device__ float  g_xr[(size_t)N_NODES * HC];        // 25.6 MB
__device__ float4 g_sumattr4[(size_t)N_NODES * FIN / 4];  // 10.24 MB
__device__ int    g_cnt[N_NODES];
__device__ float  g_p[(size_t)N_EDGES * NHEAD];      // 12.8 MB  exp(score) per edge
__device__ float  g_pself[(size_t)N_NODES * NHEAD];
__device__ float  g_denom[(size_t)N_NODES * NHEAD];
__device__ float  g_acc[(size_t)N_NODES * CH];
__device__ float  g_gsum[B_GRAPHS * CH];
__device__ int    g_gcnt[B_GRAPHS];

// ---------------- zero scratch ----------------
__global__ void zero_bufs() {
    int i0 = blockIdx.x * blockDim.x + threadIdx.x;
    int stride = gridDim.x * blockDim.x;
    float4 z4 = make_float4(0.f, 0.f, 0.f, 0.f);
    for (int i = i0; i < N_NODES * FIN / 4; i += stride) g_sumattr4[i] = z4;
    for (int i = i0; i < N_NODES; i += stride) g_cnt[i] = 0;
    for (int i = i0; i < N_NODES * NHEAD; i += stride) g_denom[i] = 0.f;
    for (int i = i0; i < N_NODES * CH; i += stride) g_acc[i] = 0.f;
    for (int i = i0; i < B_GRAPHS * CH; i += stride) g_gsum[i] = 0.f;
    for (int i = i0; i < B_GRAPHS; i += stride) g_gcnt[i] = 0;
}

// ---------------- segment-sum of edge_attr by dst (vector red) ----------------
__device__ __forceinline__ void red_add_f4(float4* addr, float4 v) {
    asm volatile("red.global.add.v4.f32 [%0], {%1,%2,%3,%4};"
                 :: "l"(addr), "f"(v.x), "f"(v.y), "f"(v.z), "f"(v.w) : "memory");
}

__global__ void scatter_attr(const float* __restrict__ ea, const int* __restrict__ ei) {
    int t = blockIdx.x * blockDim.x + threadIdx.x;
    int edge = t >> 5;
    int lane = t & 31;
    if (edge >= N_EDGES) return;
    int dst = ei[N_EDGES + edge];
    float4 v = ((const float4*)(ea + (size_t)edge * FIN))[lane];
    red_add_f4(&g_sumattr4[(size_t)dst * (FIN / 4) + lane], v);
    if (lane == 0) atomicAdd(&g_cnt[dst], 1);
}

// ---------------- tf32 helpers (proven R6-R14) ----------------
__device__ __forceinline__ uint32_t to_tf32(float x) {
    uint32_t r;
    asm("cvt.rna.tf32.f32 %0, %1;" : "=r"(r) : "f"(x));
    return r;
}

#define MMA_TF32(c, a, b)                                                      \
    asm volatile(                                                              \
        "mma.sync.aligned.m16n8k8.row.col.f32.tf32.tf32.f32 "                  \
        "{%0,%1,%2,%3}, {%4,%5,%6,%7}, {%8,%9}, {%0,%1,%2,%3};"                \
        : "+f"(c[0]), "+f"(c[1]), "+f"(c[2]), "+f"(c[3])                       \
        : "r"(a[0]), "r"(a[1]), "r"(a[2]), "r"(a[3]), "r"(b[0]), "r"(b[1]))

#define BSTRIDE 168

// ---------------- x_l / x_r tf32 tensor-core GEMM (BN fused in A staging) -------
// A = BN(x) [N x 128], B = Wl or Wr [128 x 320] (selected by n-block).
// Clone of the R14-proven tf32 score_gemm mainloop; plain store epilogue.
__global__ __launch_bounds__(256, 2)
void xlr_mma(const float* __restrict__ Asrc,
             const float* __restrict__ Wl, const float* __restrict__ Wr,
             const float* __restrict__ bl, const float* __restrict__ br,
             const float* __restrict__ bn_g, const float* __restrict__ bn_b,
             const float* __restrict__ bn_m, const float* __restrict__ bn_v) {
    __shared__ float sm[7680];            // As[64][36] + Bs[32][168]
    __shared__ float s_bnsc[FIN], s_bnsh[FIN];
    uint32_t* Asu = (uint32_t*)sm;
    uint32_t* Bsu = (uint32_t*)sm + 2304;

    const int tid = threadIdx.x;
    const int row0 = blockIdx.x * 64;
    const int n0 = blockIdx.y * 160;      // 0..639 over [Wl | Wr]
    const int warp = tid >> 5, lane = tid & 31;
    const int g = lane >> 2, tg = lane & 3;
    const int wm = warp >> 2, wn = warp & 3;

    const float* Bptr;
    const float* biasp;
    int ncol0;
    if (n0 < HC) { Bptr = Wl; biasp = bl; ncol0 = n0; }
    else         { Bptr = Wr; biasp = br; ncol0 = n0 - HC; }

    if (tid < FIN) {
        float sc = bn_g[tid] * rsqrtf(bn_v[tid] + BN_EPS);
        s_bnsc[tid] = sc;
        s_bnsh[tid] = bn_b[tid] - bn_m[tid] * sc;
    }

    float acc[2][5][4];
#pragma unroll
    for (int mi = 0; mi < 2; mi++)
#pragma unroll
        for (int nt = 0; nt < 5; nt++)
#pragma unroll
            for (int q = 0; q < 4; q++) acc[mi][nt][q] = 0.f;

    for (int kc = 0; kc < FIN; kc += 32) {
        __syncthreads();
        // --- stage A tile with BN: [64 rows][32 k], stride 36
#pragma unroll
        for (int j = 0; j < 2; j++) {
            int i = tid + j * 256;
            int r = i >> 3;
            int c4 = i & 7;
            int grow = row0 + r;
            float4 v = make_float4(0.f, 0.f, 0.f, 0.f);
            if (grow < N_NODES) {
                v = *(const float4*)(Asrc + (size_t)grow * FIN + kc + c4 * 4);
                int kb = kc + c4 * 4;
                v.x = v.x * s_bnsc[kb + 0] + s_bnsh[kb + 0];
                v.y = v.y * s_bnsc[kb + 1] + s_bnsh[kb + 1];
                v.z = v.z * s_bnsc[kb + 2] + s_bnsh[kb + 2];
                v.w = v.w * s_bnsc[kb + 3] + s_bnsh[kb + 3];
            }
            uint4 u;
            u.x = to_tf32(v.x); u.y = to_tf32(v.y); u.z = to_tf32(v.z); u.w = to_tf32(v.w);
            *(uint4*)(Asu + r * 36 + c4 * 4) = u;
        }
        // --- stage B tile: [32 k][160 n], stride 168
#pragma unroll
        for (int j = 0; j < 5; j++) {
            int i = tid + j * 256;
            int kk = i / 40;
            int n4 = i % 40;
            float4 v = *(const float4*)(Bptr + (size_t)(kc + kk) * HC + ncol0 + n4 * 4);
            uint4 u;
            u.x = to_tf32(v.x); u.y = to_tf32(v.y); u.z = to_tf32(v.z); u.w = to_tf32(v.w);
            *(uint4*)(Bsu + kk * BSTRIDE + n4 * 4) = u;
        }
        __syncthreads();

#pragma unroll
        for (int k8 = 0; k8 < 32; k8 += 8) {
            uint32_t a[2][4], b[5][2];
#pragma unroll
            for (int mi = 0; mi < 2; mi++) {
                int m = wm * 32 + mi * 16;
                a[mi][0] = Asu[(m + g) * 36 + k8 + tg];
                a[mi][1] = Asu[(m + g + 8) * 36 + k8 + tg];
                a[mi][2] = Asu[(m + g) * 36 + k8 + tg + 4];
                a[mi][3] = Asu[(m + g + 8) * 36 + k8 + tg + 4];
            }
#pragma unroll
            for (int nt = 0; nt < 5; nt++) {
                int n = wn * 40 + nt * 8 + g;
                b[nt][0] = Bsu[(k8 + tg) * BSTRIDE + n];
                b[nt][1] = Bsu[(k8 + tg + 4) * BSTRIDE + n];
            }
#pragma unroll
            for (int mi = 0; mi < 2; mi++)
#pragma unroll
                for (int nt = 0; nt < 5; nt++)
                    MMA_TF32(acc[mi][nt], a[mi], b[nt]);
        }
    }

    // --- store epilogue: x_l / x_r + bias ---
    float* outp = (n0 < HC) ? g_xl : g_xr;
#pragma unroll
    for (int mi = 0; mi < 2; mi++) {
#pragma unroll
        for (int dr = 0; dr < 2; dr++) {
            int grow = row0 + wm * 32 + mi * 16 + g + dr * 8;
            if (grow >= N_NODES) continue;
#pragma unroll
            for (int nt = 0; nt < 5; nt++) {
                int cB = wn * 40 + nt * 8 + 2 * tg;
                float2 v;
                v.x = acc[mi][nt][dr * 2 + 0] + biasp[ncol0 + cB];
                v.y = acc[mi][nt][dr * 2 + 1] + biasp[ncol0 + cB + 1];
                *(float2*)(outp + (size_t)grow * HC + ncol0 + cB) = v;
            }
        }
    }
}

// ---------------- bf16 tensor-core score GEMM + fused attention epilogue ----------
// MODE 1: A = edge_attr [E x 128] @ W_e ; MODE 2: A = sumattr/cnt [N x 128] @ W_e
// A (bf16 pair-packed, full K=128) resident in smem. B staged in 2 chunks of K=64.

__device__ __forceinline__ uint32_t pack_bf16x2(float lo, float hi) {
    uint32_t r;
    asm("cvt.rn.bf16x2.f32 %0, %1, %2;" : "=r"(r) : "f"(hi), "f"(lo));
    return r;
}

#define MMA_BF16(c, a, b)                                                      \
    asm volatile(                                                              \
        "mma.sync.aligned.m16n8k16.row.col.f32.bf16.bf16.f32 "                 \
        "{%0,%1,%2,%3}, {%4,%5,%6,%7}, {%8,%9}, {%0,%1,%2,%3};"                \
        : "+f"(c[0]), "+f"(c[1]), "+f"(c[2]), "+f"(c[3])                       \
        : "r"(a[0]), "r"(a[1]), "r"(a[2]), "r"(a[3]), "r"(b[0]), "r"(b[1]))

#define ASTRIDE16 68     // A: [64 rows][64 k-pairs + 4 pad]; frag banks 4g+tg (clean)
#define BSTRIDE16 168    // B: [32 k-pairs][160 n + 8 pad]; frag banks 8tg+g (clean)

template <int MODE>
__global__ __launch_bounds__(256, 2)
void score_gemm(const float* __restrict__ Asrc, const float* __restrict__ We,
                const float* __restrict__ att, const int* __restrict__ ei) {
    __shared__ float sm[10560];           // As16 4352u + Bs16 5376u = 9728u; zsm[64][165]
    __shared__ int s_src[64], s_dst[64];
    __shared__ float s_rinv[64];
    uint32_t* As16 = (uint32_t*)sm;            // [64][68] bf16x2
    uint32_t* Bs16 = (uint32_t*)sm + 4352;     // [32][168] bf16x2

    const int tid = threadIdx.x;
    const int row0 = blockIdx.x * 64;
    const int n0 = blockIdx.y * 160;
    const int warp = tid >> 5, lane = tid & 31;
    const int g = lane >> 2, tg = lane & 3;
    const int wm = warp >> 2, wn = warp & 3;

    if (MODE == 1) {
        if (tid < 64) {
            s_src[tid] = ei[row0 + tid];
            s_dst[tid] = ei[N_EDGES + row0 + tid];
        }
    } else {
        if (tid < 64) {
            int node = row0 + tid;
            int ok = (node < N_NODES);
            int c = ok ? g_cnt[node] : 1;
            if (c < 1) c = 1;
            s_rinv[tid] = 1.0f / (float)c;
            s_src[tid] = ok ? node : 0;
            s_dst[tid] = s_src[tid];
        }
    }
    __syncthreads();                      // s_rinv visible for MODE 2 A staging

    // ---- stage ALL of A (64 rows x K=128) as bf16 pairs, ONCE ----
#pragma unroll
    for (int j = 0; j < 8; j++) {
        int i = tid + j * 256;            // 0..2047 float4 slots
        int r = i >> 5;                   // row 0..63
        int c4 = i & 31;                  // float4 index along K
        float4 v;
        if (MODE == 1) {
            v = *(const float4*)(Asrc + (size_t)(row0 + r) * FIN + c4 * 4);
        } else {
            int grow = row0 + r;
            if (grow < N_NODES) {
                v = *(const float4*)((const float*)g_sumattr4 + (size_t)grow * FIN + c4 * 4);
                float s = s_rinv[r];
                v.x *= s; v.y *= s; v.z *= s; v.w *= s;
            } else {
                v = make_float4(0.f, 0.f, 0.f, 0.f);
            }
        }
        uint2 u;
        u.x = pack_bf16x2(v.x, v.y);
        u.y = pack_bf16x2(v.z, v.w);
        *(uint2*)(As16 + r * ASTRIDE16 + c4 * 2) = u;
    }

    float acc[2][5][4];
#pragma unroll
    for (int mi = 0; mi < 2; mi++)
#pragma unroll
        for (int nt = 0; nt < 5; nt++)
#pragma unroll
            for (int q = 0; q < 4; q++) acc[mi][nt][q] = 0.f;

    for (int kc = 0; kc < FIN; kc += 64) {
        __syncthreads();                  // prev chunk's B fully consumed
        // ---- stage B chunk [K=64 -> 32 pairs][160 n] (L2-resident W_e) ----
#pragma unroll
        for (int j = 0; j < 5; j++) {
            int i = tid + j * 256;        // 0..1279 uint4 slots
            if (i < 1280) {
                int p = i / 40;           // k-pair 0..31
                int n4 = i % 40;
                const float* bp = We + (size_t)(kc + 2 * p) * HC + n0 + n4 * 4;
                float4 r0 = *(const float4*)bp;
                float4 r1 = *(const float4*)(bp + HC);
                uint4 u;
                u.x = pack_bf16x2(r0.x, r1.x);
                u.y = pack_bf16x2(r0.y, r1.y);
                u.z = pack_bf16x2(r0.z, r1.z);
                u.w = pack_bf16x2(r0.w, r1.w);
                *(uint4*)(Bs16 + p * BSTRIDE16 + n4 * 4) = u;
            }
        }
        __syncthreads();

        const int pbase = kc >> 1;        // A pair base for this chunk
#pragma unroll
        for (int s = 0; s < 4; s++) {     // four k16 steps per chunk
            uint32_t a[2][4], b[5][2];
#pragma unroll
            for (int mi = 0; mi < 2; mi++) {
                int m = wm * 32 + mi * 16;
                a[mi][0] = As16[(m + g) * ASTRIDE16 + pbase + s * 8 + tg];
                a[mi][1] = As16[(m + g + 8) * ASTRIDE16 + pbase + s * 8 + tg];
                a[mi][2] = As16[(m + g) * ASTRIDE16 + pbase + s * 8 + tg + 4];
                a[mi][3] = As16[(m + g + 8) * ASTRIDE16 + pbase + s * 8 + tg + 4];
            }
#pragma unroll
            for (int nt = 0; nt < 5; nt++) {
                int n = wn * 40 + nt * 8 + g;
                b[nt][0] = Bs16[(s * 8 + tg) * BSTRIDE16 + n];
                b[nt][1] = Bs16[(s * 8 + tg + 4) * BSTRIDE16 + n];
            }
#pragma unroll
            for (int mi = 0; mi < 2; mi++)
#pragma unroll
                for (int nt = 0; nt < 5; nt++)
                    MMA_BF16(acc[mi][nt], a[mi], b[nt]);
        }
    }
    __syncthreads();

    // --- epilogue: z = leaky(e + xl[src] + xr[dst]); stage z*att into zsm (stride 165)
    float* zsm = sm;
#pragma unroll
    for (int mi = 0; mi < 2; mi++) {
        int r0 = wm * 32 + mi * 16 + g;        // rows r0 and r0+8
        int s0 = s_src[r0], d0 = s_dst[r0];
        int s1 = s_src[r0 + 8], d1 = s_dst[r0 + 8];
        const float* xl0 = g_xl + (size_t)s0 * HC + n0;
        const float* xr0 = g_xr + (size_t)d0 * HC + n0;
        const float* xl1 = g_xl + (size_t)s1 * HC + n0;
        const float* xr1 = g_xr + (size_t)d1 * HC + n0;
#pragma unroll
        for (int nt = 0; nt < 5; nt++) {
            int cB = wn * 40 + nt * 8 + 2 * tg;
            float at0 = att[n0 + cB], at1 = att[n0 + cB + 1];
            float z;
            z = acc[mi][nt][0] + xl0[cB] + xr0[cB];
            z = (z > 0.f) ? z : NEG_SLOPE * z;
            zsm[r0 * 165 + cB] = z * at0;
            z = acc[mi][nt][1] + xl0[cB + 1] + xr0[cB + 1];
            z = (z > 0.f) ? z : NEG_SLOPE * z;
            zsm[r0 * 165 + cB + 1] = z * at1;
            z = acc[mi][nt][2] + xl1[cB] + xr1[cB];
            z = (z > 0.f) ? z : NEG_SLOPE * z;
            zsm[(r0 + 8) * 165 + cB] = z * at0;
            z = acc[mi][nt][3] + xl1[cB + 1] + xr1[cB + 1];
            z = (z > 0.f) ? z : NEG_SLOPE * z;
            zsm[(r0 + 8) * 165 + cB + 1] = z * at1;
        }
    }
    __syncthreads();

    // --- per (row, head) sum over 32 channels -> p = exp(score); denom atomics
    for (int task = tid; task < 320; task += 256) {
        int row = task & 63;
        int hh = task >> 6;                    // 0..4 (this n-half covers 5 heads)
        float s = 0.f;
#pragma unroll
        for (int i = 0; i < 32; i++) s += zsm[row * 165 + hh * 32 + i];
        float p = __expf(s);
        int hg = blockIdx.y * 5 + hh;
        if (MODE == 1) {
            int e = row0 + row;
            g_p[(size_t)e * NHEAD + hg] = p;
            atomicAdd(&g_denom[(size_t)s_dst[row] * NHEAD + hg], p);
        } else {
            int node = row0 + row;
            if (node < N_NODES) {
                g_pself[(size_t)node * NHEAD + hg] = p;
                atomicAdd(&g_denom[(size_t)node * NHEAD + hg], p);
            }
        }
    }
}

// ---------------- edge message pass: acc[dst] += sum_h alpha_h * xl[src,h,:] ----------------
__global__ void edge_msg(const int* __restrict__ ei) {
    int gwarp = (blockIdx.x * blockDim.x + threadIdx.x) >> 5;
    int lane = threadIdx.x & 31;
    if (gwarp >= N_EDGES) return;
    int src = ei[gwarp];
    int dst = ei[N_EDGES + gwarp];
    float alpha = 0.f;
    if (lane < NHEAD)
        alpha = g_p[(size_t)gwarp * NHEAD + lane] / g_denom[(size_t)dst * NHEAD + lane];
    const float* xl = g_xl + (size_t)src * HC;
    float m = 0.f;
#pragma unroll
    for (int h = 0; h < NHEAD; h++) {
        float a = __shfl_sync(0xffffffff, alpha, h);
        m += a * xl[h * CH + lane];
    }
    atomicAdd(&g_acc[(size_t)dst * CH + lane], m);
}

// ---------------- node finalize + global mean pool (smem-staged atomics) ----------------
__global__ void finalize_pool(const int* __restrict__ batch, const float* __restrict__ bias_gat) {
    __shared__ float s_gsum[B_GRAPHS * CH];
    __shared__ int s_gcnt[B_GRAPHS];
    int tid = threadIdx.x;
    for (int i = tid; i < B_GRAPHS * CH; i += 256) s_gsum[i] = 0.f;
    if (tid < B_GRAPHS) s_gcnt[tid] = 0;
    __syncthreads();

    int warp = tid >> 5, lane = tid & 31;
    for (int u = 0; u < 8; u++) {
        int node = blockIdx.x * 64 + warp * 8 + u;
        if (node < N_NODES) {
            int b = batch[node];
            float a = 0.f;
            if (lane < NHEAD)
                a = g_pself[(size_t)node * NHEAD + lane] / g_denom[(size_t)node * NHEAD + lane];
            const float* xl = g_xl + (size_t)node * HC;
            float selfm = 0.f;
#pragma unroll
            for (int h = 0; h < NHEAD; h++) {
                float ah = __shfl_sync(0xffffffff, a, h);
                selfm += ah * xl[h * CH + lane];
            }
            float v = (g_acc[(size_t)node * CH + lane] + selfm) * (1.0f / NHEAD) + bias_gat[lane];
            v = fmaxf(v, 0.f);
            atomicAdd(&s_gsum[b * CH + lane], v);
            if (lane == 0) atomicAdd(&s_gcnt[b], 1);
        }
    }
    __syncthreads();
    for (int i = tid; i < B_GRAPHS * CH; i += 256)
        if (s_gsum[i] != 0.f) atomicAdd(&g_gsum[i], s_gsum[i]);
    if (tid < B_GRAPHS && s_gcnt[tid] != 0) atomicAdd(&g_gcnt[tid], s_gcnt[tid]);
}

// ---------------- head: out[b, o] = (gsum[b]/cnt[b]) @ W_head + b_head ----------------
__global__ void head_kernel(const float* __restrict__ Wh, const float* __restrict__ bh,
                            float* __restrict__ out) {
    int t = threadIdx.x;
    if (t < B_GRAPHS * 2) {
        int b = t >> 1, o = t & 1;
        int c = g_gcnt[b]; if (c < 1) c = 1;
        float inv = 1.0f / (float)c;
        float s = 0.f;
#pragma unroll
        for (int k = 0; k < CH; k++) s += (g_gsum[b * CH + k] * inv) * Wh[k * 2 + o];
        out[t] = s + bh[o];
    }
}

extern "C" void kernel_launch(void* const* d_in, const int* in_sizes, int n_in,
                              void* d_out, int out_size) {
    const float* x        = (const float*)d_in[0];
    const int*   ei       = (const int*)d_in[1];
    const float* ea       = (const float*)d_in[2];
    const int*   batch    = (const int*)d_in[3];
    const float* bn_g     = (const float*)d_in[4];
    const float* bn_b     = (const float*)d_in[5];
    const float* bn_m     = (const float*)d_in[6];
    const float* bn_v     = (const float*)d_in[7];
    const float* Wl       = (const float*)d_in[8];
    const float* bl       = (const float*)d_in[9];
    const float* Wr       = (const float*)d_in[10];
    const float* br       = (const float*)d_in[11];
    const float* We       = (const float*)d_in[12];
    const float* att      = (const float*)d_in[13];
    const float* bias_gat = (const float*)d_in[14];
    const float* Wh       = (const float*)d_in[15];
    const float* bh       = (const float*)d_in[16];
    float* out = (float*)d_out;

    zero_bufs<<<512, 256>>>();
    scatter_attr<<<(N_EDGES * 32) / 256, 256>>>(ea, ei);
    // x_l / x_r : tf32 tensor cores, BN fused in A staging
    xlr_mma<<<dim3(313, 4), 256>>>(x, Wl, Wr, bl, br, bn_g, bn_b, bn_m, bn_v);
    // self-loop scores (bf16 tensor cores)
    score_gemm<2><<<dim3(313, 2), 256>>>(nullptr, We, att, ei);
    // edge scores (26-GFLOP GEMM, bf16 tensor cores, A-resident, K=64 B chunks)
    score_gemm<1><<<dim3(5000, 2), 256>>>(ea, We, att, ei);
    edge_msg<<<(N_EDGES * 32) / 256, 256>>>(ei);
    finalize_pool<<<313, 256>>>(batch, bias_gat);
    head_kernel<<<1, 128>>>(Wh, bh, out);
}